// round 6
// baseline (speedup 1.0000x reference)
#include <cuda_runtime.h>
#include <math.h>
#include <stdint.h>

// ---------------- constants ----------------
#define TL   1024     // T_LEN
#define DM   1024     // DIM
#define DI   2048     // D_INNER
#define DS   16       // D_STATE
#define TROWS (1024 + 512 + 256)   // packed time rows across 3 scales

// ---------------- scratch (no cudaMalloc allowed) ----------------
__device__ float g_xz   [TL * 4096];          // xz = [x_in | gate]
__device__ float g_xc   [TROWS * DI];
__device__ float g_dt   [TROWS * DI];
__device__ float g_bc   [TROWS * 32];
__device__ float g_y    [TROWS * DI];
__device__ float g_fused[TL * DI];
__device__ float g_ctx  [TL * DI];
__device__ float g_g1   [TL * 1024];
__device__ float g_pre  [TL * DI];
__device__ float g_yln  [TL * DM];

// ---------------- helpers ----------------
static __device__ __forceinline__ float softplusf(float x) {
    return fmaxf(x, 0.0f) + log1pf(expf(-fabsf(x)));
}

static __device__ __forceinline__ void cp_async16(void* smem_dst, const void* gsrc) {
    uint32_t s = (uint32_t)__cvta_generic_to_shared(smem_dst);
    asm volatile("cp.async.cg.shared.global [%0], [%1], 16;\n" :: "r"(s), "l"(gsrc));
}
static __device__ __forceinline__ void cp_commit() {
    asm volatile("cp.async.commit_group;\n");
}
static __device__ __forceinline__ void cp_wait1() {
    asm volatile("cp.async.wait_group 1;\n" ::: "memory");
}

static __device__ __forceinline__ void mma_tf32(float* d, const uint32_t* a, const uint32_t* b) {
    asm volatile(
        "mma.sync.aligned.m16n8k8.row.col.f32.tf32.tf32.f32 "
        "{%0,%1,%2,%3}, {%4,%5,%6,%7}, {%8,%9}, {%0,%1,%2,%3};"
        : "+f"(d[0]), "+f"(d[1]), "+f"(d[2]), "+f"(d[3])
        : "r"(a[0]), "r"(a[1]), "r"(a[2]), "r"(a[3]), "r"(b[0]), "r"(b[1]));
}

// ---------------- TF32 tensor-core GEMM: C[M,N] = A[M,K] * W[N,K]^T ----------
// Block tile BM x BN, BK=32, 3-stage cp.async ring, 256 threads = 8 warps (2x4),
// warp tile (BM/2) x (BN/4). fp32 raw bits fed to tf32 mma (HW truncation).
enum { EPI_NONE = 0, EPI_SILU = 1, EPI_GATE = 2, EPI_RES = 3 };

#define SKS 36   // smem row stride in floats (32 + 4 pad)

template <int EPI, int BM, int BN>
__global__ __launch_bounds__(256)
void gemm_tc(const float* __restrict__ A, int lda,
             const float* __restrict__ W, int ldw,
             float* __restrict__ C, int ldc, int K,
             const float* __restrict__ aux1, int ld1,
             const float* __restrict__ aux2, int ld2)
{
    constexpr int MT  = BM / 32;              // mmas in m per warp
    constexpr int NT  = BN / 32;              // mmas in n per warp
    constexpr int NA4 = BM * 8 / 256;         // float4 copies per thread for A
    constexpr int NW4 = BN * 8 / 256;         // float4 copies per thread for W
    extern __shared__ __align__(16) float smem[];
    float* Asm = smem;                        // [3][BM][SKS]
    float* Wsm = smem + 3 * BM * SKS;         // [3][BN][SKS]

    const int tid  = threadIdx.x;
    const int lane = tid & 31;
    const int wid  = tid >> 5;
    const int m0   = blockIdx.y * BM;
    const int n0   = blockIdx.x * BN;
    const int wm   = (wid >> 2) * (BM / 2);
    const int wn   = (wid & 3) * (BN / 4);
    const int gid  = lane >> 2;
    const int tig  = lane & 3;

    float acc[MT][NT][4];
#pragma unroll
    for (int i = 0; i < MT; i++)
#pragma unroll
        for (int j = 0; j < NT; j++)
#pragma unroll
            for (int q = 0; q < 4; q++) acc[i][j][q] = 0.0f;

    const int KT = K >> 5;   // K/32 tiles

    auto issue = [&](int kt, int st) {
        const float* Ag = A + (size_t)m0 * lda + kt * 32;
        const float* Wg = W + (size_t)n0 * ldw + kt * 32;
        float* As = Asm + st * BM * SKS;
        float* Ws = Wsm + st * BN * SKS;
#pragma unroll
        for (int i = 0; i < NA4; i++) {
            int idx4 = tid + i * 256;
            int row = idx4 >> 3;
            int col = (idx4 & 7) << 2;
            cp_async16(&As[row * SKS + col], Ag + (size_t)row * lda + col);
        }
#pragma unroll
        for (int i = 0; i < NW4; i++) {
            int idx4 = tid + i * 256;
            int row = idx4 >> 3;
            int col = (idx4 & 7) << 2;
            cp_async16(&Ws[row * SKS + col], Wg + (size_t)row * ldw + col);
        }
    };

    issue(0, 0); cp_commit();
    issue(1, 1); cp_commit();

    for (int kt = 0; kt < KT; kt++) {
        const int st = kt % 3;
        cp_wait1();            // tile kt resident (tile kt+1 may still fly)
        __syncthreads();

        if (kt + 2 < KT) issue(kt + 2, (kt + 2) % 3);
        cp_commit();           // commit every iter (possibly empty) for group math

        const float* As = Asm + st * BM * SKS;
        const float* Ws = Wsm + st * BN * SKS;

#pragma unroll
        for (int kk = 0; kk < 32; kk += 8) {
            uint32_t af[MT][4];
            uint32_t bf[NT][2];
#pragma unroll
            for (int mt = 0; mt < MT; mt++) {
                int r = wm + (mt << 4) + gid;
                af[mt][0] = __float_as_uint(As[r * SKS + kk + tig]);
                af[mt][1] = __float_as_uint(As[(r + 8) * SKS + kk + tig]);
                af[mt][2] = __float_as_uint(As[r * SKS + kk + tig + 4]);
                af[mt][3] = __float_as_uint(As[(r + 8) * SKS + kk + tig + 4]);
            }
#pragma unroll
            for (int nt = 0; nt < NT; nt++) {
                int n = wn + (nt << 3) + gid;
                bf[nt][0] = __float_as_uint(Ws[n * SKS + kk + tig]);
                bf[nt][1] = __float_as_uint(Ws[n * SKS + kk + tig + 4]);
            }
#pragma unroll
            for (int mt = 0; mt < MT; mt++)
#pragma unroll
                for (int nt = 0; nt < NT; nt++)
                    mma_tf32(acc[mt][nt], af[mt], bf[nt]);
        }
    }

    // ---- epilogue ----
#pragma unroll
    for (int mt = 0; mt < MT; mt++) {
#pragma unroll
        for (int nt = 0; nt < NT; nt++) {
            int row0 = m0 + wm + (mt << 4) + gid;
            int col  = n0 + wn + (nt << 3) + (tig << 1);
#pragma unroll
            for (int half = 0; half < 2; half++) {
                int m = row0 + half * 8;
                float v0 = acc[mt][nt][half * 2 + 0];
                float v1 = acc[mt][nt][half * 2 + 1];
                if (EPI == EPI_SILU) {
                    v0 = v0 / (1.0f + expf(-v0));
                    v1 = v1 / (1.0f + expf(-v1));
                } else if (EPI == EPI_GATE) {
                    float f0 = aux1[(size_t)m * ld1 + col];
                    float f1 = aux1[(size_t)m * ld1 + col + 1];
                    float g0 = aux2[(size_t)m * ld2 + col];
                    float g1 = aux2[(size_t)m * ld2 + col + 1];
                    v0 = f0 * (1.0f / (1.0f + expf(-v0))) * (g0 / (1.0f + expf(-g0)));
                    v1 = f1 * (1.0f / (1.0f + expf(-v1))) * (g1 / (1.0f + expf(-g1)));
                } else if (EPI == EPI_RES) {
                    v0 += aux1[(size_t)m * ld1 + col];
                    v1 += aux1[(size_t)m * ld1 + col + 1];
                }
                *reinterpret_cast<float2*>(&C[(size_t)m * ldc + col]) = make_float2(v0, v1);
            }
        }
    }
}

// ---------------- causal dwconv (K=4) + silu, all scales, downsample fused --
__global__ void conv_all_kernel(const float* __restrict__ xz,
                                const float* __restrict__ cw,   // [3][DI][4]
                                const float* __restrict__ cb,   // [3][DI]
                                float* __restrict__ xc)
{
    int idx = blockIdx.x * blockDim.x + threadIdx.x;   // over 1792*2048
    if (idx >= TROWS * DI) return;
    int d = idx & (DI - 1);
    int r = idx >> 11;

    int s, t;
    if (r < 1024)      { s = 0; t = r;        }
    else if (r < 1536) { s = 1; t = r - 1024; }
    else               { s = 2; t = r - 1536; }

    // gather x_s[t-3..t][d] with on-the-fly downsample from xz (row stride 4096)
    float xv[4];
#pragma unroll
    for (int k = 0; k < 4; k++) {
        int tt = t - 3 + k;
        float v = 0.0f;
        if (tt >= 0) {
            if (s == 0) {
                v = xz[(size_t)tt * 4096 + d];
            } else if (s == 1) {
                v = 0.5f * (xz[(size_t)(2 * tt) * 4096 + d] +
                            xz[(size_t)(2 * tt + 1) * 4096 + d]);
            } else {
                float acc4 = 0.0f;
#pragma unroll
                for (int q = 0; q < 4; q++)
                    acc4 += xz[(size_t)(4 * tt + q) * 4096 + d];
                v = 0.25f * acc4;
            }
        }
        xv[k] = v;
    }

    float4 w = *reinterpret_cast<const float4*>(cw + ((size_t)s * DI + d) * 4);
    float acc = cb[s * DI + d];
    acc = fmaf(xv[0], w.x, acc);
    acc = fmaf(xv[1], w.y, acc);
    acc = fmaf(xv[2], w.z, acc);
    acc = fmaf(xv[3], w.w, acc);
    xc[idx] = acc / (1.0f + expf(-acc));   // silu
}

// ---------------- xproj: bc[r,32] = xc[r,:] @ xw_s[32,DI]^T ----------------
// warp = one row; lane = one output column. No shuffles, float4 over K.
__global__ __launch_bounds__(256)
void xproj_all_kernel(const float* __restrict__ xc, const float* __restrict__ xproj_w,
                      float* __restrict__ bc)
{
    int r = blockIdx.x * 8 + (threadIdx.x >> 5);   // 0..1791
    int j = threadIdx.x & 31;
    int s = (r < 1024) ? 0 : (r < 1536 ? 1 : 2);
    const float* wrow = xproj_w + (size_t)s * 32 * DI + (size_t)j * DI;
    const float* row  = xc + (size_t)r * DI;

    float a0 = 0.f, a1 = 0.f;
    for (int k = 0; k < DI; k += 8) {
        float4 x0 = *reinterpret_cast<const float4*>(row + k);
        float4 x1 = *reinterpret_cast<const float4*>(row + k + 4);
        float4 w0 = *reinterpret_cast<const float4*>(wrow + k);
        float4 w1 = *reinterpret_cast<const float4*>(wrow + k + 4);
        a0 = fmaf(x0.x, w0.x, a0); a0 = fmaf(x0.y, w0.y, a0);
        a0 = fmaf(x0.z, w0.z, a0); a0 = fmaf(x0.w, w0.w, a0);
        a1 = fmaf(x1.x, w1.x, a1); a1 = fmaf(x1.y, w1.y, a1);
        a1 = fmaf(x1.z, w1.z, a1); a1 = fmaf(x1.w, w1.w, a1);
    }
    bc[r * 32 + j] = a0 + a1;
}

// ---------------- dt = softplus(softplus(B @ dtw^T + dtb)), all scales ----
__global__ void dt_all_kernel(const float* __restrict__ bc, const float* __restrict__ dtproj_w,
                              const float* __restrict__ dtproj_b, float* __restrict__ dt)
{
    int idx = blockIdx.x * blockDim.x + threadIdx.x;
    if (idx >= TROWS * DI) return;
    int d = idx & (DI - 1);
    int r = idx >> 11;
    int s = (r < 1024) ? 0 : (r < 1536 ? 1 : 2);
    const float* Brow = bc + r * 32;
    const float* wrow = dtproj_w + ((size_t)s * DI + d) * 16;
    float acc = dtproj_b[s * DI + d];
#pragma unroll
    for (int n = 0; n < DS; n++) acc = fmaf(Brow[n], wrow[n], acc);
    dt[idx] = softplusf(softplusf(acc));
}

// ---------------- SSM scan (all 3 scales in one launch, 1-iter prefetch) ----
__global__ __launch_bounds__(256)
void scan_all_kernel(const float* __restrict__ dtb_, const float* __restrict__ xcb_,
                     const float* __restrict__ bcb_, const float* __restrict__ Dp_,
                     float* __restrict__ yb_)
{
    int gw   = (blockIdx.x * 256 + threadIdx.x) >> 5;   // 0..3071
    int s    = gw >> 10;                                 // scale 0..2
    int w    = gw & 1023;
    int lane = threadIdx.x & 31;
    int d    = w * 2 + (lane >> 4);
    int n    = lane & 15;
    int T    = 1024 >> s;

    const int xo  = (s == 0) ? 0 : (s == 1 ? 1024 * DI : 1536 * DI);
    const int bco = (s == 0) ? 0 : (s == 1 ? 1024 * 32 : 1536 * 32);

    const float* dt = dtb_ + xo;
    const float* xc = xcb_ + xo;
    const float* bc = bcb_ + bco;
    float*       y  = yb_ + xo;

    const float A  = -(float)(n + 1);
    const float Dv = Dp_[s * DI + d];

    float h = 0.0f;
    float dtv = dt[d];
    float xcv = xc[d];
    float Bv  = bc[n];
    float Cv  = bc[16 + n];

    for (int t = 0; t < T; t++) {
        float dtn = 0.f, xcn = 0.f, Bn = 0.f, Cn = 0.f;
        if (t + 1 < T) {
            dtn = dt[(size_t)(t + 1) * DI + d];
            xcn = xc[(size_t)(t + 1) * DI + d];
            Bn  = bc[(t + 1) * 32 + n];
            Cn  = bc[(t + 1) * 32 + 16 + n];
        }
        float a = __expf(dtv * A);
        a = fmaxf(a, 1e-38f);
        float b = dtv * Bv * xcv;
        b = fmaxf(b, 1e-38f);
        h = fmaf(a, h, b);
        float c = Cv * h;
        c += __shfl_xor_sync(0xffffffffu, c, 8);
        c += __shfl_xor_sync(0xffffffffu, c, 4);
        c += __shfl_xor_sync(0xffffffffu, c, 2);
        c += __shfl_xor_sync(0xffffffffu, c, 1);
        if (n == 0) y[(size_t)t * DI + d] = c + Dv * xcv;
        dtv = dtn; xcv = xcn; Bv = Bn; Cv = Cn;
    }
}

// ---------------- fuse: upsample + softmax-weighted sum + ctx ----------------
__global__ void fuse_kernel(const float* __restrict__ y0, const float* __restrict__ y1,
                            const float* __restrict__ y2, const float* __restrict__ sw,
                            float* __restrict__ fused, float* __restrict__ ctx)
{
    int idx = blockIdx.x * blockDim.x + threadIdx.x;
    if (idx >= TL * DI) return;
    int d = idx & (DI - 1);
    int t = idx >> 11;

    float w0 = sw[0], w1 = sw[1], w2 = sw[2];
    float m = fmaxf(w0, fmaxf(w1, w2));
    float e0 = expf(w0 - m), e1 = expf(w1 - m), e2 = expf(w2 - m);
    float inv = 1.0f / (e0 + e1 + e2);

    float o0 = y0[idx];

    float p1 = (t + 0.5f) * 0.5f - 0.5f;
    p1 = fminf(fmaxf(p1, 0.0f), 511.0f);
    int lo1 = (int)floorf(p1);
    int hi1 = min(lo1 + 1, 511);
    float f1 = p1 - (float)lo1;
    float o1 = y1[(size_t)lo1 * DI + d] * (1.0f - f1) + y1[(size_t)hi1 * DI + d] * f1;

    float p2 = (t + 0.5f) * 0.25f - 0.5f;
    p2 = fminf(fmaxf(p2, 0.0f), 255.0f);
    int lo2 = (int)floorf(p2);
    int hi2 = min(lo2 + 1, 255);
    float f2 = p2 - (float)lo2;
    float o2 = y2[(size_t)lo2 * DI + d] * (1.0f - f2) + y2[(size_t)hi2 * DI + d] * f2;

    fused[idx] = (e0 * o0 + e1 * o1 + e2 * o2) * inv;
    ctx[idx]   = (o0 + o1 + o2) * (1.0f / 3.0f);
}

// ---------------- layernorm over last dim (1024) ----------------
__global__ __launch_bounds__(256)
void layernorm_kernel(const float* __restrict__ Y, const float* __restrict__ g,
                      const float* __restrict__ b, float* __restrict__ out)
{
    int t = blockIdx.x;
    int tid = threadIdx.x;
    const float* row = Y + (size_t)t * DM;
    float4 v = *reinterpret_cast<const float4*>(row + tid * 4);
    float s = (v.x + v.y) + (v.z + v.w);
    __shared__ float sh[8];
#pragma unroll
    for (int o = 16; o > 0; o >>= 1) s += __shfl_xor_sync(0xffffffffu, s, o);
    if ((tid & 31) == 0) sh[tid >> 5] = s;
    __syncthreads();
    float tot = 0.0f;
#pragma unroll
    for (int i = 0; i < 8; i++) tot += sh[i];
    float mu = tot * (1.0f / 1024.0f);
    float dx0 = v.x - mu, dx1 = v.y - mu, dx2 = v.z - mu, dx3 = v.w - mu;
    float q = dx0 * dx0 + dx1 * dx1 + dx2 * dx2 + dx3 * dx3;
    __syncthreads();
#pragma unroll
    for (int o = 16; o > 0; o >>= 1) q += __shfl_xor_sync(0xffffffffu, q, o);
    if ((tid & 31) == 0) sh[tid >> 5] = q;
    __syncthreads();
    float qt = 0.0f;
#pragma unroll
    for (int i = 0; i < 8; i++) qt += sh[i];
    float var = qt * (1.0f / 1024.0f);
    float invs = rsqrtf(var + 1e-5f);
    float4 gg = *reinterpret_cast<const float4*>(g + tid * 4);
    float4 bb = *reinterpret_cast<const float4*>(b + tid * 4);
    float4 o4;
    o4.x = dx0 * invs * gg.x + bb.x;
    o4.y = dx1 * invs * gg.y + bb.y;
    o4.z = dx2 * invs * gg.z + bb.z;
    o4.w = dx3 * invs * gg.w + bb.w;
    *reinterpret_cast<float4*>(out + (size_t)t * DM + tid * 4) = o4;
}

// ---------------- launch ----------------
extern "C" void kernel_launch(void* const* d_in, const int* in_sizes, int n_in,
                              void* d_out, int out_size)
{
    (void)in_sizes; (void)n_in; (void)out_size;
    const float* x          = (const float*)d_in[0];
    const float* in_proj_w  = (const float*)d_in[1];
    const float* conv_w     = (const float*)d_in[2];
    const float* conv_b     = (const float*)d_in[3];
    const float* xproj_w    = (const float*)d_in[4];
    const float* dtproj_w   = (const float*)d_in[5];
    const float* dtproj_b   = (const float*)d_in[6];
    const float* D_param    = (const float*)d_in[7];
    const float* sw         = (const float*)d_in[8];
    const float* gate_w1    = (const float*)d_in[9];
    const float* gate_w2    = (const float*)d_in[10];
    const float* out_proj_w = (const float*)d_in[11];
    const float* ln_g       = (const float*)d_in[12];
    const float* ln_b       = (const float*)d_in[13];
    float* out = (float*)d_out;

    float *xz, *xc, *dt, *bc, *yb, *fused, *ctx, *g1, *pre, *yln;
    cudaGetSymbolAddress((void**)&xz,    g_xz);
    cudaGetSymbolAddress((void**)&xc,    g_xc);
    cudaGetSymbolAddress((void**)&dt,    g_dt);
    cudaGetSymbolAddress((void**)&bc,    g_bc);
    cudaGetSymbolAddress((void**)&yb,    g_y);
    cudaGetSymbolAddress((void**)&fused, g_fused);
    cudaGetSymbolAddress((void**)&ctx,   g_ctx);
    cudaGetSymbolAddress((void**)&g1,    g_g1);
    cudaGetSymbolAddress((void**)&pre,   g_pre);
    cudaGetSymbolAddress((void**)&yln,   g_yln);

    const int smem256 = 3 * (128 + 256) * SKS * 4;   // 165888 B
    const int smem64  = 3 * (64 + 128) * SKS * 4;    //  82944 B
    cudaFuncSetAttribute(gemm_tc<EPI_NONE, 128, 256>, cudaFuncAttributeMaxDynamicSharedMemorySize, smem256);
    cudaFuncSetAttribute(gemm_tc<EPI_SILU, 64, 128>,  cudaFuncAttributeMaxDynamicSharedMemorySize, smem64);
    cudaFuncSetAttribute(gemm_tc<EPI_GATE, 64, 128>,  cudaFuncAttributeMaxDynamicSharedMemorySize, smem64);
    cudaFuncSetAttribute(gemm_tc<EPI_RES, 64, 128>,   cudaFuncAttributeMaxDynamicSharedMemorySize, smem64);

    // 1) in_proj: xz[1024,4096] = x @ in_proj_w^T   (128 blocks = one wave)
    gemm_tc<EPI_NONE, 128, 256><<<dim3(4096 / 256, 1024 / 128), 256, smem256>>>(
        x, 1024, in_proj_w, 1024, xz, 4096, 1024, nullptr, 0, nullptr, 0);

    // 2) causal dwconv + silu (all scales, downsample fused inline)
    conv_all_kernel<<<(TROWS * DI + 255) / 256, 256>>>(xz, conv_w, conv_b, xc);

    // 3) xproj (warp-per-row, lane-per-col)
    xproj_all_kernel<<<TROWS / 8, 256>>>(xc, xproj_w, bc);

    // 4) dt (all scales)
    dt_all_kernel<<<(TROWS * DI + 255) / 256, 256>>>(bc, dtproj_w, dtproj_b, dt);

    // 5) scan (all scales)
    scan_all_kernel<<<384, 256>>>(dt, xc, bc, D_param, yb);

    // 6) fuse (upsample + weighted sum + ctx)
    fuse_kernel<<<(TL * DI + 255) / 256, 256>>>(yb, yb + 1024 * DI, yb + 1536 * DI,
                                                sw, fused, ctx);

    // 7) gate path + output projection
    gemm_tc<EPI_SILU, 64, 128><<<dim3(1024 / 128, 1024 / 64), 256, smem64>>>(
        ctx, DI, gate_w1, DI, g1, 1024, DI, nullptr, 0, nullptr, 0);
    gemm_tc<EPI_GATE, 64, 128><<<dim3(2048 / 128, 1024 / 64), 256, smem64>>>(
        g1, 1024, gate_w2, 1024, pre, DI, 1024, fused, DI, xz + 2048, 4096);
    gemm_tc<EPI_RES, 64, 128><<<dim3(1024 / 128, 1024 / 64), 256, smem64>>>(
        pre, DI, out_proj_w, DI, yln, 1024, DI, x, 1024, nullptr, 0);

    // 8) layernorm -> d_out
    layernorm_kernel<<<1024, 256>>>(yln, ln_g, ln_b, out);
}

// round 13
// speedup vs baseline: 1.1279x; 1.1279x over previous
#include <cuda_runtime.h>
#include <math.h>
#include <stdint.h>

// ---------------- constants ----------------
#define TL   1024     // T_LEN
#define DM   1024     // DIM
#define DI   2048     // D_INNER
#define DS   16       // D_STATE
#define TROWS (1024 + 512 + 256)   // packed time rows across 3 scales

// ---------------- scratch (no cudaMalloc allowed) ----------------
__device__ float g_xz   [TL * 4096];          // xz = [x_in | gate]
__device__ float g_xs1  [512 * DI];
__device__ float g_xs2  [256 * DI];
__device__ float g_xc   [TROWS * DI];
__device__ float g_dt   [TROWS * DI];
__device__ float g_bc   [TROWS * 32];
__device__ float g_y    [TROWS * DI];
__device__ float g_fused[TL * DI];
__device__ float g_ctx  [TL * DI];
__device__ float g_g1   [TL * 1024];
__device__ float g_pre  [TL * DI];
__device__ float g_yln  [TL * DM];

// ---------------- helpers ----------------
static __device__ __forceinline__ float softplusf(float x) {
    return fmaxf(x, 0.0f) + log1pf(expf(-fabsf(x)));
}

static __device__ __forceinline__ void cp_async16(void* smem_dst, const void* gsrc) {
    uint32_t s = (uint32_t)__cvta_generic_to_shared(smem_dst);
    asm volatile("cp.async.cg.shared.global [%0], [%1], 16;\n" :: "r"(s), "l"(gsrc));
}
static __device__ __forceinline__ void cp_commit() {
    asm volatile("cp.async.commit_group;\n");
}
static __device__ __forceinline__ void cp_wait1() {
    asm volatile("cp.async.wait_group 1;\n" ::: "memory");
}

static __device__ __forceinline__ void mma_tf32(float* d, const uint32_t* a, const uint32_t* b) {
    asm volatile(
        "mma.sync.aligned.m16n8k8.row.col.f32.tf32.tf32.f32 "
        "{%0,%1,%2,%3}, {%4,%5,%6,%7}, {%8,%9}, {%0,%1,%2,%3};"
        : "+f"(d[0]), "+f"(d[1]), "+f"(d[2]), "+f"(d[3])
        : "r"(a[0]), "r"(a[1]), "r"(a[2]), "r"(a[3]), "r"(b[0]), "r"(b[1]));
}

// ---------------- TF32 tensor-core GEMM: C[M,N] = A[M,K] * W[N,K]^T ----------
// Block tile BM x 128, BK=32, 3-stage cp.async ring, 256 threads = 8 warps (2x4),
// warp tile (BM/2) x 32. fp32 raw bits fed to tf32 mma (HW truncation).
enum { EPI_NONE = 0, EPI_SILU = 1, EPI_GATE = 2, EPI_RES = 3 };

#define SKS 36   // smem row stride in floats (32 + 4 pad)

template <int EPI, int BM>
__global__ __launch_bounds__(256)
void gemm_tc(const float* __restrict__ A, int lda,
             const float* __restrict__ W, int ldw,
             float* __restrict__ C, int ldc, int K,
             const float* __restrict__ aux1, int ld1,
             const float* __restrict__ aux2, int ld2)
{
    constexpr int MT  = BM / 32;              // mmas in m per warp
    constexpr int NA4 = BM * 8 / 256;         // float4 copies per thread for A
    extern __shared__ __align__(16) float smem[];
    float* Asm = smem;                        // [3][BM][SKS]
    float* Wsm = smem + 3 * BM * SKS;         // [3][128][SKS]

    const int tid  = threadIdx.x;
    const int lane = tid & 31;
    const int wid  = tid >> 5;
    const int m0   = blockIdx.y * BM;
    const int n0   = blockIdx.x << 7;
    const int wm   = (wid >> 2) * (BM / 2);
    const int wn   = (wid & 3) << 5;
    const int gid  = lane >> 2;
    const int tig  = lane & 3;

    float acc[MT][4][4];
#pragma unroll
    for (int i = 0; i < MT; i++)
#pragma unroll
        for (int j = 0; j < 4; j++)
#pragma unroll
            for (int q = 0; q < 4; q++) acc[i][j][q] = 0.0f;

    const int KT = K >> 5;   // K/32 tiles

    auto issue = [&](int kt, int st) {
        const float* Ag = A + (size_t)m0 * lda + kt * 32;
        const float* Wg = W + (size_t)n0 * ldw + kt * 32;
        float* As = Asm + st * BM * SKS;
        float* Ws = Wsm + st * 128 * SKS;
#pragma unroll
        for (int i = 0; i < NA4; i++) {
            int idx4 = tid + i * 256;
            int row = idx4 >> 3;
            int col = (idx4 & 7) << 2;
            cp_async16(&As[row * SKS + col], Ag + (size_t)row * lda + col);
        }
#pragma unroll
        for (int i = 0; i < 4; i++) {
            int idx4 = tid + i * 256;
            int row = idx4 >> 3;
            int col = (idx4 & 7) << 2;
            cp_async16(&Ws[row * SKS + col], Wg + (size_t)row * ldw + col);
        }
    };

    issue(0, 0); cp_commit();
    issue(1, 1); cp_commit();

    for (int kt = 0; kt < KT; kt++) {
        const int st = kt % 3;
        cp_wait1();            // tile kt resident (tile kt+1 may still fly)
        __syncthreads();

        if (kt + 2 < KT) issue(kt + 2, (kt + 2) % 3);
        cp_commit();           // commit every iter (possibly empty) for group math

        const float* As = Asm + st * BM * SKS;
        const float* Ws = Wsm + st * 128 * SKS;

#pragma unroll
        for (int kk = 0; kk < 32; kk += 8) {
            uint32_t af[MT][4];
            uint32_t bf[4][2];
#pragma unroll
            for (int mt = 0; mt < MT; mt++) {
                int r = wm + (mt << 4) + gid;
                af[mt][0] = __float_as_uint(As[r * SKS + kk + tig]);
                af[mt][1] = __float_as_uint(As[(r + 8) * SKS + kk + tig]);
                af[mt][2] = __float_as_uint(As[r * SKS + kk + tig + 4]);
                af[mt][3] = __float_as_uint(As[(r + 8) * SKS + kk + tig + 4]);
            }
#pragma unroll
            for (int nt = 0; nt < 4; nt++) {
                int n = wn + (nt << 3) + gid;
                bf[nt][0] = __float_as_uint(Ws[n * SKS + kk + tig]);
                bf[nt][1] = __float_as_uint(Ws[n * SKS + kk + tig + 4]);
            }
#pragma unroll
            for (int mt = 0; mt < MT; mt++)
#pragma unroll
                for (int nt = 0; nt < 4; nt++)
                    mma_tf32(acc[mt][nt], af[mt], bf[nt]);
        }
    }

    // ---- epilogue ----
#pragma unroll
    for (int mt = 0; mt < MT; mt++) {
#pragma unroll
        for (int nt = 0; nt < 4; nt++) {
            int row0 = m0 + wm + (mt << 4) + gid;
            int col  = n0 + wn + (nt << 3) + (tig << 1);
#pragma unroll
            for (int half = 0; half < 2; half++) {
                int m = row0 + half * 8;
                float v0 = acc[mt][nt][half * 2 + 0];
                float v1 = acc[mt][nt][half * 2 + 1];
                if (EPI == EPI_SILU) {
                    v0 = v0 / (1.0f + expf(-v0));
                    v1 = v1 / (1.0f + expf(-v1));
                } else if (EPI == EPI_GATE) {
                    float f0 = aux1[(size_t)m * ld1 + col];
                    float f1 = aux1[(size_t)m * ld1 + col + 1];
                    float g0 = aux2[(size_t)m * ld2 + col];
                    float g1 = aux2[(size_t)m * ld2 + col + 1];
                    v0 = f0 * (1.0f / (1.0f + expf(-v0))) * (g0 / (1.0f + expf(-g0)));
                    v1 = f1 * (1.0f / (1.0f + expf(-v1))) * (g1 / (1.0f + expf(-g1)));
                } else if (EPI == EPI_RES) {
                    v0 += aux1[(size_t)m * ld1 + col];
                    v1 += aux1[(size_t)m * ld1 + col + 1];
                }
                *reinterpret_cast<float2*>(&C[(size_t)m * ldc + col]) = make_float2(v0, v1);
            }
        }
    }
}

// ---------------- downsample both scales in one launch ----------------
__global__ void downsample_all_kernel(const float* __restrict__ Xin,  // row stride 4096
                                      float* __restrict__ xs1, float* __restrict__ xs2)
{
    int idx = blockIdx.x * blockDim.x + threadIdx.x;   // over (512+256)*2048
    if (idx >= (512 + 256) * DI) return;
    int d = idx & (DI - 1);
    int r = idx >> 11;
    if (r < 512) {
        float s = Xin[(size_t)(r * 2) * 4096 + d] + Xin[(size_t)(r * 2 + 1) * 4096 + d];
        xs1[r * DI + d] = s * 0.5f;
    } else {
        int t = r - 512;
        float s = 0.0f;
#pragma unroll
        for (int q = 0; q < 4; q++) s += Xin[(size_t)(t * 4 + q) * 4096 + d];
        xs2[t * DI + d] = s * 0.25f;
    }
}

// ---------------- causal depthwise conv (K=4) + silu, all scales ----------
__global__ void conv_all_kernel(const float* __restrict__ xz,
                                const float* __restrict__ xs1,
                                const float* __restrict__ xs2,
                                const float* __restrict__ cw,   // [3][DI][4]
                                const float* __restrict__ cb,   // [3][DI]
                                float* __restrict__ xc)
{
    int idx = blockIdx.x * blockDim.x + threadIdx.x;   // over 1792*2048
    if (idx >= TROWS * DI) return;
    int d = idx & (DI - 1);
    int r = idx >> 11;

    int s, t;
    const float* X; int ldx;
    if (r < 1024)      { s = 0; t = r;        X = xz;  ldx = 4096; }
    else if (r < 1536) { s = 1; t = r - 1024; X = xs1; ldx = DI;   }
    else               { s = 2; t = r - 1536; X = xs2; ldx = DI;   }

    float4 w = *reinterpret_cast<const float4*>(cw + ((size_t)s * DI + d) * 4);
    float acc = cb[s * DI + d];
    if (t >= 3) {
        acc = fmaf(X[(size_t)(t - 3) * ldx + d], w.x, acc);
        acc = fmaf(X[(size_t)(t - 2) * ldx + d], w.y, acc);
        acc = fmaf(X[(size_t)(t - 1) * ldx + d], w.z, acc);
        acc = fmaf(X[(size_t)t * ldx + d],       w.w, acc);
    } else {
        const float wk[4] = {w.x, w.y, w.z, w.w};
#pragma unroll
        for (int k = 0; k < 4; k++) {
            int tt = t - 3 + k;
            if (tt >= 0) acc = fmaf(X[(size_t)tt * ldx + d], wk[k], acc);
        }
    }
    xc[idx] = acc / (1.0f + expf(-acc));   // silu
}

// ---------------- xproj: bc[r,32] = xc[r,:] @ xw_s[32,DI]^T ----------------
// warp = one row; lane = one output column. No shuffles, float4 over K.
__global__ __launch_bounds__(256)
void xproj_all_kernel(const float* __restrict__ xc, const float* __restrict__ xproj_w,
                      float* __restrict__ bc)
{
    int r = blockIdx.x * 8 + (threadIdx.x >> 5);   // 0..1791
    int j = threadIdx.x & 31;
    int s = (r < 1024) ? 0 : (r < 1536 ? 1 : 2);
    const float* wrow = xproj_w + (size_t)s * 32 * DI + (size_t)j * DI;
    const float* row  = xc + (size_t)r * DI;

    float a0 = 0.f, a1 = 0.f;
    for (int k = 0; k < DI; k += 8) {
        float4 x0 = *reinterpret_cast<const float4*>(row + k);
        float4 x1 = *reinterpret_cast<const float4*>(row + k + 4);
        float4 w0 = *reinterpret_cast<const float4*>(wrow + k);
        float4 w1 = *reinterpret_cast<const float4*>(wrow + k + 4);
        a0 = fmaf(x0.x, w0.x, a0); a0 = fmaf(x0.y, w0.y, a0);
        a0 = fmaf(x0.z, w0.z, a0); a0 = fmaf(x0.w, w0.w, a0);
        a1 = fmaf(x1.x, w1.x, a1); a1 = fmaf(x1.y, w1.y, a1);
        a1 = fmaf(x1.z, w1.z, a1); a1 = fmaf(x1.w, w1.w, a1);
    }
    bc[r * 32 + j] = a0 + a1;
}

// ---------------- dt: tiled, weight-reuse version (staging FIXED) ----------
// block = 256 threads = 256 channels; 16 rows per block.
// grid.x = TROWS/16 (row tiles, never crossing scale boundary), grid.y = DI/256.
__global__ __launch_bounds__(256)
void dt_all_kernel(const float* __restrict__ bc, const float* __restrict__ dtproj_w,
                   const float* __restrict__ dtproj_b, float* __restrict__ dt)
{
    __shared__ float Bs[16][32];

    const int r0 = blockIdx.x * 16;
    const int d  = blockIdx.y * 256 + threadIdx.x;
    const int s  = (r0 < 1024) ? 0 : (r0 < 1536 ? 1 : 2);

    // stage the 16 bc rows: 512 floats, 256 threads -> 2 each (coalesced)
#pragma unroll
    for (int i = threadIdx.x; i < 16 * 32; i += 256) {
        Bs[i >> 5][i & 31] = bc[(r0 + (i >> 5)) * 32 + (i & 31)];
    }

    // per-thread weights: 16 floats, loaded once, reused over 16 rows
    const float* wrow = dtproj_w + ((size_t)s * DI + d) * 16;
    float4 w0 = *reinterpret_cast<const float4*>(wrow);
    float4 w1 = *reinterpret_cast<const float4*>(wrow + 4);
    float4 w2 = *reinterpret_cast<const float4*>(wrow + 8);
    float4 w3 = *reinterpret_cast<const float4*>(wrow + 12);
    const float bias = dtproj_b[s * DI + d];

    __syncthreads();

#pragma unroll 4
    for (int rr = 0; rr < 16; rr++) {
        const float* B = Bs[rr];
        float acc = bias;
        acc = fmaf(B[0],  w0.x, acc); acc = fmaf(B[1],  w0.y, acc);
        acc = fmaf(B[2],  w0.z, acc); acc = fmaf(B[3],  w0.w, acc);
        acc = fmaf(B[4],  w1.x, acc); acc = fmaf(B[5],  w1.y, acc);
        acc = fmaf(B[6],  w1.z, acc); acc = fmaf(B[7],  w1.w, acc);
        acc = fmaf(B[8],  w2.x, acc); acc = fmaf(B[9],  w2.y, acc);
        acc = fmaf(B[10], w2.z, acc); acc = fmaf(B[11], w2.w, acc);
        acc = fmaf(B[12], w3.x, acc); acc = fmaf(B[13], w3.y, acc);
        acc = fmaf(B[14], w3.z, acc); acc = fmaf(B[15], w3.w, acc);
        dt[(size_t)(r0 + rr) * DI + d] = softplusf(softplusf(acc));
    }
}

// ---------------- SSM scan (all 3 scales in one launch, 1-iter prefetch) ----
__global__ __launch_bounds__(256)
void scan_all_kernel(const float* __restrict__ dtb_, const float* __restrict__ xcb_,
                     const float* __restrict__ bcb_, const float* __restrict__ Dp_,
                     float* __restrict__ yb_)
{
    int gw   = (blockIdx.x * 256 + threadIdx.x) >> 5;   // 0..3071
    int s    = gw >> 10;                                 // scale 0..2
    int w    = gw & 1023;
    int lane = threadIdx.x & 31;
    int d    = w * 2 + (lane >> 4);
    int n    = lane & 15;
    int T    = 1024 >> s;

    const int xo  = (s == 0) ? 0 : (s == 1 ? 1024 * DI : 1536 * DI);
    const int bco = (s == 0) ? 0 : (s == 1 ? 1024 * 32 : 1536 * 32);

    const float* dt = dtb_ + xo;
    const float* xc = xcb_ + xo;
    const float* bc = bcb_ + bco;
    float*       y  = yb_ + xo;

    const float A  = -(float)(n + 1);
    const float Dv = Dp_[s * DI + d];

    float h = 0.0f;
    float dtv = dt[d];
    float xcv = xc[d];
    float Bv  = bc[n];
    float Cv  = bc[16 + n];

    for (int t = 0; t < T; t++) {
        float dtn = 0.f, xcn = 0.f, Bn = 0.f, Cn = 0.f;
        if (t + 1 < T) {
            dtn = dt[(size_t)(t + 1) * DI + d];
            xcn = xc[(size_t)(t + 1) * DI + d];
            Bn  = bc[(t + 1) * 32 + n];
            Cn  = bc[(t + 1) * 32 + 16 + n];
        }
        float a = __expf(dtv * A);
        a = fmaxf(a, 1e-38f);
        float b = dtv * Bv * xcv;
        b = fmaxf(b, 1e-38f);
        h = fmaf(a, h, b);
        float c = Cv * h;
        c += __shfl_xor_sync(0xffffffffu, c, 8);
        c += __shfl_xor_sync(0xffffffffu, c, 4);
        c += __shfl_xor_sync(0xffffffffu, c, 2);
        c += __shfl_xor_sync(0xffffffffu, c, 1);
        if (n == 0) y[(size_t)t * DI + d] = c + Dv * xcv;
        dtv = dtn; xcv = xcn; Bv = Bn; Cv = Cn;
    }
}

// ---------------- fuse: upsample + softmax-weighted sum + ctx ----------------
__global__ void fuse_kernel(const float* __restrict__ y0, const float* __restrict__ y1,
                            const float* __restrict__ y2, const float* __restrict__ sw,
                            float* __restrict__ fused, float* __restrict__ ctx)
{
    int idx = blockIdx.x * blockDim.x + threadIdx.x;
    if (idx >= TL * DI) return;
    int d = idx & (DI - 1);
    int t = idx >> 11;

    float w0 = sw[0], w1 = sw[1], w2 = sw[2];
    float m = fmaxf(w0, fmaxf(w1, w2));
    float e0 = expf(w0 - m), e1 = expf(w1 - m), e2 = expf(w2 - m);
    float inv = 1.0f / (e0 + e1 + e2);

    float o0 = y0[idx];

    float p1 = (t + 0.5f) * 0.5f - 0.5f;
    p1 = fminf(fmaxf(p1, 0.0f), 511.0f);
    int lo1 = (int)floorf(p1);
    int hi1 = min(lo1 + 1, 511);
    float f1 = p1 - (float)lo1;
    float o1 = y1[(size_t)lo1 * DI + d] * (1.0f - f1) + y1[(size_t)hi1 * DI + d] * f1;

    float p2 = (t + 0.5f) * 0.25f - 0.5f;
    p2 = fminf(fmaxf(p2, 0.0f), 255.0f);
    int lo2 = (int)floorf(p2);
    int hi2 = min(lo2 + 1, 255);
    float f2 = p2 - (float)lo2;
    float o2 = y2[(size_t)lo2 * DI + d] * (1.0f - f2) + y2[(size_t)hi2 * DI + d] * f2;

    fused[idx] = (e0 * o0 + e1 * o1 + e2 * o2) * inv;
    ctx[idx]   = (o0 + o1 + o2) * (1.0f / 3.0f);
}

// ---------------- layernorm over last dim (1024) ----------------
__global__ __launch_bounds__(256)
void layernorm_kernel(const float* __restrict__ Y, const float* __restrict__ g,
                      const float* __restrict__ b, float* __restrict__ out)
{
    int t = blockIdx.x;
    int tid = threadIdx.x;
    const float* row = Y + (size_t)t * DM;
    float4 v = *reinterpret_cast<const float4*>(row + tid * 4);
    float s = (v.x + v.y) + (v.z + v.w);
    __shared__ float sh[8];
#pragma unroll
    for (int o = 16; o > 0; o >>= 1) s += __shfl_xor_sync(0xffffffffu, s, o);
    if ((tid & 31) == 0) sh[tid >> 5] = s;
    __syncthreads();
    float tot = 0.0f;
#pragma unroll
    for (int i = 0; i < 8; i++) tot += sh[i];
    float mu = tot * (1.0f / 1024.0f);
    float dx0 = v.x - mu, dx1 = v.y - mu, dx2 = v.z - mu, dx3 = v.w - mu;
    float q = dx0 * dx0 + dx1 * dx1 + dx2 * dx2 + dx3 * dx3;
    __syncthreads();
#pragma unroll
    for (int o = 16; o > 0; o >>= 1) q += __shfl_xor_sync(0xffffffffu, q, o);
    if ((tid & 31) == 0) sh[tid >> 5] = q;
    __syncthreads();
    float qt = 0.0f;
#pragma unroll
    for (int i = 0; i < 8; i++) qt += sh[i];
    float var = qt * (1.0f / 1024.0f);
    float invs = rsqrtf(var + 1e-5f);
    float4 gg = *reinterpret_cast<const float4*>(g + tid * 4);
    float4 bb = *reinterpret_cast<const float4*>(b + tid * 4);
    float4 o4;
    o4.x = dx0 * invs * gg.x + bb.x;
    o4.y = dx1 * invs * gg.y + bb.y;
    o4.z = dx2 * invs * gg.z + bb.z;
    o4.w = dx3 * invs * gg.w + bb.w;
    *reinterpret_cast<float4*>(out + (size_t)t * DM + tid * 4) = o4;
}

// ---------------- launch ----------------
extern "C" void kernel_launch(void* const* d_in, const int* in_sizes, int n_in,
                              void* d_out, int out_size)
{
    (void)in_sizes; (void)n_in; (void)out_size;
    const float* x          = (const float*)d_in[0];
    const float* in_proj_w  = (const float*)d_in[1];
    const float* conv_w     = (const float*)d_in[2];
    const float* conv_b     = (const float*)d_in[3];
    const float* xproj_w    = (const float*)d_in[4];
    const float* dtproj_w   = (const float*)d_in[5];
    const float* dtproj_b   = (const float*)d_in[6];
    const float* D_param    = (const float*)d_in[7];
    const float* sw         = (const float*)d_in[8];
    const float* gate_w1    = (const float*)d_in[9];
    const float* gate_w2    = (const float*)d_in[10];
    const float* out_proj_w = (const float*)d_in[11];
    const float* ln_g       = (const float*)d_in[12];
    const float* ln_b       = (const float*)d_in[13];
    float* out = (float*)d_out;

    float *xz, *xs1, *xs2, *xc, *dt, *bc, *yb, *fused, *ctx, *g1, *pre, *yln;
    cudaGetSymbolAddress((void**)&xz,    g_xz);
    cudaGetSymbolAddress((void**)&xs1,   g_xs1);
    cudaGetSymbolAddress((void**)&xs2,   g_xs2);
    cudaGetSymbolAddress((void**)&xc,    g_xc);
    cudaGetSymbolAddress((void**)&dt,    g_dt);
    cudaGetSymbolAddress((void**)&bc,    g_bc);
    cudaGetSymbolAddress((void**)&yb,    g_y);
    cudaGetSymbolAddress((void**)&fused, g_fused);
    cudaGetSymbolAddress((void**)&ctx,   g_ctx);
    cudaGetSymbolAddress((void**)&g1,    g_g1);
    cudaGetSymbolAddress((void**)&pre,   g_pre);
    cudaGetSymbolAddress((void**)&yln,   g_yln);

    const int smem128 = 3 * (128 + 128) * SKS * 4;   // 110592 B
    const int smem64  = 3 * (64 + 128) * SKS * 4;    //  82944 B
    cudaFuncSetAttribute(gemm_tc<EPI_NONE, 128>, cudaFuncAttributeMaxDynamicSharedMemorySize, smem128);
    cudaFuncSetAttribute(gemm_tc<EPI_SILU, 64>,  cudaFuncAttributeMaxDynamicSharedMemorySize, smem64);
    cudaFuncSetAttribute(gemm_tc<EPI_GATE, 64>,  cudaFuncAttributeMaxDynamicSharedMemorySize, smem64);
    cudaFuncSetAttribute(gemm_tc<EPI_RES, 64>,   cudaFuncAttributeMaxDynamicSharedMemorySize, smem64);

    // 1) in_proj: xz[1024,4096] = x @ in_proj_w^T
    gemm_tc<EPI_NONE, 128><<<dim3(4096 / 128, 1024 / 128), 256, smem128>>>(
        x, 1024, in_proj_w, 1024, xz, 4096, 1024, nullptr, 0, nullptr, 0);

    // 2) downsample (both scales)
    downsample_all_kernel<<<((512 + 256) * DI + 255) / 256, 256>>>(xz, xs1, xs2);

    // 3) causal dwconv + silu (all scales)
    conv_all_kernel<<<(TROWS * DI + 255) / 256, 256>>>(xz, xs1, xs2, conv_w, conv_b, xc);

    // 4) xproj (warp-per-row, lane-per-col)
    xproj_all_kernel<<<TROWS / 8, 256>>>(xc, xproj_w, bc);

    // 5) dt (tiled with weight reuse)
    dt_all_kernel<<<dim3(TROWS / 16, DI / 256), 256>>>(bc, dtproj_w, dtproj_b, dt);

    // 6) scan (all scales)
    scan_all_kernel<<<384, 256>>>(dt, xc, bc, D_param, yb);

    // 7) fuse (upsample + weighted sum + ctx)
    fuse_kernel<<<(TL * DI + 255) / 256, 256>>>(yb, yb + 1024 * DI, yb + 1536 * DI,
                                                sw, fused, ctx);

    // 8) gate path + output projection
    gemm_tc<EPI_SILU, 64><<<dim3(1024 / 128, 1024 / 64), 256, smem64>>>(
        ctx, DI, gate_w1, DI, g1, 1024, DI, nullptr, 0, nullptr, 0);
    gemm_tc<EPI_GATE, 64><<<dim3(2048 / 128, 1024 / 64), 256, smem64>>>(
        g1, 1024, gate_w2, 1024, pre, DI, 1024, fused, DI, xz + 2048, 4096);
    gemm_tc<EPI_RES, 64><<<dim3(1024 / 128, 1024 / 64), 256, smem64>>>(
        pre, DI, out_proj_w, DI, yln, 1024, DI, x, 1024, nullptr, 0);

    // 9) layernorm -> d_out
    layernorm_kernel<<<1024, 256>>>(yln, ln_g, ln_b, out);
}

// round 14
// speedup vs baseline: 1.2581x; 1.1155x over previous
#include <cuda_runtime.h>
#include <math.h>
#include <stdint.h>

// ---------------- constants ----------------
#define TL   1024     // T_LEN
#define DM   1024     // DIM
#define DI   2048     // D_INNER
#define DS   16       // D_STATE
#define TROWS (1024 + 512 + 256)   // packed time rows across 3 scales

// ---------------- scratch (no cudaMalloc allowed) ----------------
__device__ float g_xz   [TL * 4096];          // xz = [x_in | gate]
__device__ float g_xs1  [512 * DI];
__device__ float g_xs2  [256 * DI];
__device__ float g_xc   [TROWS * DI];
__device__ float g_dt   [TROWS * DI];
__device__ float g_bc   [TROWS * 32];
__device__ float g_y    [TROWS * DI];
__device__ float g_fused[TL * DI];
__device__ float g_ctx  [TL * DI];
__device__ float g_g1   [TL * 1024];
__device__ float g_pre  [TL * DI];
__device__ float g_yln  [TL * DM];

// ---------------- helpers ----------------
static __device__ __forceinline__ float softplusf(float x) {
    return fmaxf(x, 0.0f) + log1pf(expf(-fabsf(x)));
}

static __device__ __forceinline__ void cp_async16(void* smem_dst, const void* gsrc) {
    uint32_t s = (uint32_t)__cvta_generic_to_shared(smem_dst);
    asm volatile("cp.async.cg.shared.global [%0], [%1], 16;\n" :: "r"(s), "l"(gsrc));
}
static __device__ __forceinline__ void cp_commit() {
    asm volatile("cp.async.commit_group;\n");
}
static __device__ __forceinline__ void cp_wait1() {
    asm volatile("cp.async.wait_group 1;\n" ::: "memory");
}

static __device__ __forceinline__ void mma_tf32(float* d, const uint32_t* a, const uint32_t* b) {
    asm volatile(
        "mma.sync.aligned.m16n8k8.row.col.f32.tf32.tf32.f32 "
        "{%0,%1,%2,%3}, {%4,%5,%6,%7}, {%8,%9}, {%0,%1,%2,%3};"
        : "+f"(d[0]), "+f"(d[1]), "+f"(d[2]), "+f"(d[3])
        : "r"(a[0]), "r"(a[1]), "r"(a[2]), "r"(a[3]), "r"(b[0]), "r"(b[1]));
}

// ---------------- TF32 tensor-core GEMM: C[M,N] = A[M,K] * W[N,K]^T ----------
// Block tile BM x 128, BK=32, 3-stage cp.async ring, 256 threads = 8 warps (2x4),
// warp tile (BM/2) x 32. fp32 raw bits fed to tf32 mma (HW truncation).
enum { EPI_NONE = 0, EPI_SILU = 1, EPI_GATE = 2, EPI_RES = 3 };

#define SKS 36   // smem row stride in floats (32 + 4 pad)

template <int EPI, int BM>
__global__ __launch_bounds__(256)
void gemm_tc(const float* __restrict__ A, int lda,
             const float* __restrict__ W, int ldw,
             float* __restrict__ C, int ldc, int K,
             const float* __restrict__ aux1, int ld1,
             const float* __restrict__ aux2, int ld2)
{
    constexpr int MT  = BM / 32;              // mmas in m per warp
    constexpr int NA4 = BM * 8 / 256;         // float4 copies per thread for A
    extern __shared__ __align__(16) float smem[];
    float* Asm = smem;                        // [3][BM][SKS]
    float* Wsm = smem + 3 * BM * SKS;         // [3][128][SKS]

    const int tid  = threadIdx.x;
    const int lane = tid & 31;
    const int wid  = tid >> 5;
    const int m0   = blockIdx.y * BM;
    const int n0   = blockIdx.x << 7;
    const int wm   = (wid >> 2) * (BM / 2);
    const int wn   = (wid & 3) << 5;
    const int gid  = lane >> 2;
    const int tig  = lane & 3;

    float acc[MT][4][4];
#pragma unroll
    for (int i = 0; i < MT; i++)
#pragma unroll
        for (int j = 0; j < 4; j++)
#pragma unroll
            for (int q = 0; q < 4; q++) acc[i][j][q] = 0.0f;

    const int KT = K >> 5;   // K/32 tiles

    auto issue = [&](int kt, int st) {
        const float* Ag = A + (size_t)m0 * lda + kt * 32;
        const float* Wg = W + (size_t)n0 * ldw + kt * 32;
        float* As = Asm + st * BM * SKS;
        float* Ws = Wsm + st * 128 * SKS;
#pragma unroll
        for (int i = 0; i < NA4; i++) {
            int idx4 = tid + i * 256;
            int row = idx4 >> 3;
            int col = (idx4 & 7) << 2;
            cp_async16(&As[row * SKS + col], Ag + (size_t)row * lda + col);
        }
#pragma unroll
        for (int i = 0; i < 4; i++) {
            int idx4 = tid + i * 256;
            int row = idx4 >> 3;
            int col = (idx4 & 7) << 2;
            cp_async16(&Ws[row * SKS + col], Wg + (size_t)row * ldw + col);
        }
    };

    issue(0, 0); cp_commit();
    issue(1, 1); cp_commit();

    for (int kt = 0; kt < KT; kt++) {
        const int st = kt % 3;
        cp_wait1();            // tile kt resident (tile kt+1 may still fly)
        __syncthreads();

        if (kt + 2 < KT) issue(kt + 2, (kt + 2) % 3);
        cp_commit();           // commit every iter (possibly empty) for group math

        const float* As = Asm + st * BM * SKS;
        const float* Ws = Wsm + st * 128 * SKS;

#pragma unroll
        for (int kk = 0; kk < 32; kk += 8) {
            uint32_t af[MT][4];
            uint32_t bf[4][2];
#pragma unroll
            for (int mt = 0; mt < MT; mt++) {
                int r = wm + (mt << 4) + gid;
                af[mt][0] = __float_as_uint(As[r * SKS + kk + tig]);
                af[mt][1] = __float_as_uint(As[(r + 8) * SKS + kk + tig]);
                af[mt][2] = __float_as_uint(As[r * SKS + kk + tig + 4]);
                af[mt][3] = __float_as_uint(As[(r + 8) * SKS + kk + tig + 4]);
            }
#pragma unroll
            for (int nt = 0; nt < 4; nt++) {
                int n = wn + (nt << 3) + gid;
                bf[nt][0] = __float_as_uint(Ws[n * SKS + kk + tig]);
                bf[nt][1] = __float_as_uint(Ws[n * SKS + kk + tig + 4]);
            }
#pragma unroll
            for (int mt = 0; mt < MT; mt++)
#pragma unroll
                for (int nt = 0; nt < 4; nt++)
                    mma_tf32(acc[mt][nt], af[mt], bf[nt]);
        }
    }

    // ---- epilogue ----
#pragma unroll
    for (int mt = 0; mt < MT; mt++) {
#pragma unroll
        for (int nt = 0; nt < 4; nt++) {
            int row0 = m0 + wm + (mt << 4) + gid;
            int col  = n0 + wn + (nt << 3) + (tig << 1);
#pragma unroll
            for (int half = 0; half < 2; half++) {
                int m = row0 + half * 8;
                float v0 = acc[mt][nt][half * 2 + 0];
                float v1 = acc[mt][nt][half * 2 + 1];
                if (EPI == EPI_SILU) {
                    v0 = v0 / (1.0f + expf(-v0));
                    v1 = v1 / (1.0f + expf(-v1));
                } else if (EPI == EPI_GATE) {
                    float f0 = aux1[(size_t)m * ld1 + col];
                    float f1 = aux1[(size_t)m * ld1 + col + 1];
                    float g0 = aux2[(size_t)m * ld2 + col];
                    float g1 = aux2[(size_t)m * ld2 + col + 1];
                    v0 = f0 * (1.0f / (1.0f + expf(-v0))) * (g0 / (1.0f + expf(-g0)));
                    v1 = f1 * (1.0f / (1.0f + expf(-v1))) * (g1 / (1.0f + expf(-g1)));
                } else if (EPI == EPI_RES) {
                    v0 += aux1[(size_t)m * ld1 + col];
                    v1 += aux1[(size_t)m * ld1 + col + 1];
                }
                *reinterpret_cast<float2*>(&C[(size_t)m * ldc + col]) = make_float2(v0, v1);
            }
        }
    }
}

// ---------------- downsample both scales in one launch ----------------
__global__ void downsample_all_kernel(const float* __restrict__ Xin,  // row stride 4096
                                      float* __restrict__ xs1, float* __restrict__ xs2)
{
    int idx = blockIdx.x * blockDim.x + threadIdx.x;   // over (512+256)*2048
    if (idx >= (512 + 256) * DI) return;
    int d = idx & (DI - 1);
    int r = idx >> 11;
    if (r < 512) {
        float s = Xin[(size_t)(r * 2) * 4096 + d] + Xin[(size_t)(r * 2 + 1) * 4096 + d];
        xs1[r * DI + d] = s * 0.5f;
    } else {
        int t = r - 512;
        float s = 0.0f;
#pragma unroll
        for (int q = 0; q < 4; q++) s += Xin[(size_t)(t * 4 + q) * 4096 + d];
        xs2[t * DI + d] = s * 0.25f;
    }
}

// ---------------- causal depthwise conv (K=4) + silu, all scales ----------
__global__ void conv_all_kernel(const float* __restrict__ xz,
                                const float* __restrict__ xs1,
                                const float* __restrict__ xs2,
                                const float* __restrict__ cw,   // [3][DI][4]
                                const float* __restrict__ cb,   // [3][DI]
                                float* __restrict__ xc)
{
    int idx = blockIdx.x * blockDim.x + threadIdx.x;   // over 1792*2048
    if (idx >= TROWS * DI) return;
    int d = idx & (DI - 1);
    int r = idx >> 11;

    int s, t;
    const float* X; int ldx;
    if (r < 1024)      { s = 0; t = r;        X = xz;  ldx = 4096; }
    else if (r < 1536) { s = 1; t = r - 1024; X = xs1; ldx = DI;   }
    else               { s = 2; t = r - 1536; X = xs2; ldx = DI;   }

    float4 w = *reinterpret_cast<const float4*>(cw + ((size_t)s * DI + d) * 4);
    float acc = cb[s * DI + d];
    if (t >= 3) {
        acc = fmaf(X[(size_t)(t - 3) * ldx + d], w.x, acc);
        acc = fmaf(X[(size_t)(t - 2) * ldx + d], w.y, acc);
        acc = fmaf(X[(size_t)(t - 1) * ldx + d], w.z, acc);
        acc = fmaf(X[(size_t)t * ldx + d],       w.w, acc);
    } else {
        const float wk[4] = {w.x, w.y, w.z, w.w};
#pragma unroll
        for (int k = 0; k < 4; k++) {
            int tt = t - 3 + k;
            if (tt >= 0) acc = fmaf(X[(size_t)tt * ldx + d], wk[k], acc);
        }
    }
    xc[idx] = acc / (1.0f + expf(-acc));   // silu
}

// ---------------- xproj: bc[r,32] = xc[r,:] @ xw_s[32,DI]^T ----------------
// Block = 8 warps = 8 rows; lane j = output col j. Weight chunks staged in
// smem (coalesced global loads, conflict-free LDS: stride 257 -> bank j+k).
#define XK 256
__global__ __launch_bounds__(256)
void xproj_all_kernel(const float* __restrict__ xc, const float* __restrict__ xproj_w,
                      float* __restrict__ bc)
{
    __shared__ float ws[32][XK + 1];   // stride 257 floats

    const int warp = threadIdx.x >> 5;
    const int j    = threadIdx.x & 31;
    const int r0   = blockIdx.x * 8;             // 1024,1536 divisible by 8: no cross
    const int r    = r0 + warp;
    const int s    = (r0 < 1024) ? 0 : (r0 < 1536 ? 1 : 2);
    const float* wbase = xproj_w + (size_t)s * 32 * DI;
    const float* xrow  = xc + (size_t)r * DI;

    float acc = 0.0f;
    for (int k0 = 0; k0 < DI; k0 += XK) {
        __syncthreads();   // previous chunk fully consumed
        // stage ws[32][XK]: 8192 floats, 256 threads x 8 float4 each, coalesced
#pragma unroll
        for (int i = threadIdx.x * 4; i < 32 * XK; i += 256 * 4) {
            int row = i >> 8;          // i / XK
            int col = i & (XK - 1);    // i % XK
            float4 v = *reinterpret_cast<const float4*>(wbase + (size_t)row * DI + k0 + col);
            ws[row][col]     = v.x;
            ws[row][col + 1] = v.y;
            ws[row][col + 2] = v.z;
            ws[row][col + 3] = v.w;
        }
        __syncthreads();
#pragma unroll 8
        for (int k = 0; k < XK; k += 4) {
            float4 xv = *reinterpret_cast<const float4*>(xrow + k0 + k);  // broadcast
            acc = fmaf(xv.x, ws[j][k],     acc);
            acc = fmaf(xv.y, ws[j][k + 1], acc);
            acc = fmaf(xv.z, ws[j][k + 2], acc);
            acc = fmaf(xv.w, ws[j][k + 3], acc);
        }
    }
    bc[r * 32 + j] = acc;
}

// ---------------- dt: tiled, weight-reuse version ----------
// block = 256 threads = 256 channels; 16 rows per block.
// grid.x = TROWS/16 (row tiles, never crossing scale boundary), grid.y = DI/256.
__global__ __launch_bounds__(256)
void dt_all_kernel(const float* __restrict__ bc, const float* __restrict__ dtproj_w,
                   const float* __restrict__ dtproj_b, float* __restrict__ dt)
{
    __shared__ float Bs[16][32];

    const int r0 = blockIdx.x * 16;
    const int d  = blockIdx.y * 256 + threadIdx.x;
    const int s  = (r0 < 1024) ? 0 : (r0 < 1536 ? 1 : 2);

    // stage the 16 bc rows: 512 floats, 256 threads -> 2 each (coalesced)
#pragma unroll
    for (int i = threadIdx.x; i < 16 * 32; i += 256) {
        Bs[i >> 5][i & 31] = bc[(r0 + (i >> 5)) * 32 + (i & 31)];
    }

    // per-thread weights: 16 floats, loaded once, reused over 16 rows
    const float* wrow = dtproj_w + ((size_t)s * DI + d) * 16;
    float4 w0 = *reinterpret_cast<const float4*>(wrow);
    float4 w1 = *reinterpret_cast<const float4*>(wrow + 4);
    float4 w2 = *reinterpret_cast<const float4*>(wrow + 8);
    float4 w3 = *reinterpret_cast<const float4*>(wrow + 12);
    const float bias = dtproj_b[s * DI + d];

    __syncthreads();

#pragma unroll 4
    for (int rr = 0; rr < 16; rr++) {
        const float* B = Bs[rr];
        float acc = bias;
        acc = fmaf(B[0],  w0.x, acc); acc = fmaf(B[1],  w0.y, acc);
        acc = fmaf(B[2],  w0.z, acc); acc = fmaf(B[3],  w0.w, acc);
        acc = fmaf(B[4],  w1.x, acc); acc = fmaf(B[5],  w1.y, acc);
        acc = fmaf(B[6],  w1.z, acc); acc = fmaf(B[7],  w1.w, acc);
        acc = fmaf(B[8],  w2.x, acc); acc = fmaf(B[9],  w2.y, acc);
        acc = fmaf(B[10], w2.z, acc); acc = fmaf(B[11], w2.w, acc);
        acc = fmaf(B[12], w3.x, acc); acc = fmaf(B[13], w3.y, acc);
        acc = fmaf(B[14], w3.z, acc); acc = fmaf(B[15], w3.w, acc);
        dt[(size_t)(r0 + rr) * DI + d] = softplusf(softplusf(acc));
    }
}

// ---------------- SSM scan (all 3 scales in one launch, 1-iter prefetch) ----
__global__ __launch_bounds__(256)
void scan_all_kernel(const float* __restrict__ dtb_, const float* __restrict__ xcb_,
                     const float* __restrict__ bcb_, const float* __restrict__ Dp_,
                     float* __restrict__ yb_)
{
    int gw   = (blockIdx.x * 256 + threadIdx.x) >> 5;   // 0..3071
    int s    = gw >> 10;                                 // scale 0..2
    int w    = gw & 1023;
    int lane = threadIdx.x & 31;
    int d    = w * 2 + (lane >> 4);
    int n    = lane & 15;
    int T    = 1024 >> s;

    const int xo  = (s == 0) ? 0 : (s == 1 ? 1024 * DI : 1536 * DI);
    const int bco = (s == 0) ? 0 : (s == 1 ? 1024 * 32 : 1536 * 32);

    const float* dt = dtb_ + xo;
    const float* xc = xcb_ + xo;
    const float* bc = bcb_ + bco;
    float*       y  = yb_ + xo;

    const float A  = -(float)(n + 1);
    const float Dv = Dp_[s * DI + d];

    float h = 0.0f;
    float dtv = dt[d];
    float xcv = xc[d];
    float Bv  = bc[n];
    float Cv  = bc[16 + n];

    for (int t = 0; t < T; t++) {
        float dtn = 0.f, xcn = 0.f, Bn = 0.f, Cn = 0.f;
        if (t + 1 < T) {
            dtn = dt[(size_t)(t + 1) * DI + d];
            xcn = xc[(size_t)(t + 1) * DI + d];
            Bn  = bc[(t + 1) * 32 + n];
            Cn  = bc[(t + 1) * 32 + 16 + n];
        }
        float a = __expf(dtv * A);
        a = fmaxf(a, 1e-38f);
        float b = dtv * Bv * xcv;
        b = fmaxf(b, 1e-38f);
        h = fmaf(a, h, b);
        float c = Cv * h;
        c += __shfl_xor_sync(0xffffffffu, c, 8);
        c += __shfl_xor_sync(0xffffffffu, c, 4);
        c += __shfl_xor_sync(0xffffffffu, c, 2);
        c += __shfl_xor_sync(0xffffffffu, c, 1);
        if (n == 0) y[(size_t)t * DI + d] = c + Dv * xcv;
        dtv = dtn; xcv = xcn; Bv = Bn; Cv = Cn;
    }
}

// ---------------- fuse: upsample + softmax-weighted sum + ctx ----------------
__global__ void fuse_kernel(const float* __restrict__ y0, const float* __restrict__ y1,
                            const float* __restrict__ y2, const float* __restrict__ sw,
                            float* __restrict__ fused, float* __restrict__ ctx)
{
    int idx = blockIdx.x * blockDim.x + threadIdx.x;
    if (idx >= TL * DI) return;
    int d = idx & (DI - 1);
    int t = idx >> 11;

    float w0 = sw[0], w1 = sw[1], w2 = sw[2];
    float m = fmaxf(w0, fmaxf(w1, w2));
    float e0 = expf(w0 - m), e1 = expf(w1 - m), e2 = expf(w2 - m);
    float inv = 1.0f / (e0 + e1 + e2);

    float o0 = y0[idx];

    float p1 = (t + 0.5f) * 0.5f - 0.5f;
    p1 = fminf(fmaxf(p1, 0.0f), 511.0f);
    int lo1 = (int)floorf(p1);
    int hi1 = min(lo1 + 1, 511);
    float f1 = p1 - (float)lo1;
    float o1 = y1[(size_t)lo1 * DI + d] * (1.0f - f1) + y1[(size_t)hi1 * DI + d] * f1;

    float p2 = (t + 0.5f) * 0.25f - 0.5f;
    p2 = fminf(fmaxf(p2, 0.0f), 255.0f);
    int lo2 = (int)floorf(p2);
    int hi2 = min(lo2 + 1, 255);
    float f2 = p2 - (float)lo2;
    float o2 = y2[(size_t)lo2 * DI + d] * (1.0f - f2) + y2[(size_t)hi2 * DI + d] * f2;

    fused[idx] = (e0 * o0 + e1 * o1 + e2 * o2) * inv;
    ctx[idx]   = (o0 + o1 + o2) * (1.0f / 3.0f);
}

// ---------------- layernorm over last dim (1024) ----------------
__global__ __launch_bounds__(256)
void layernorm_kernel(const float* __restrict__ Y, const float* __restrict__ g,
                      const float* __restrict__ b, float* __restrict__ out)
{
    int t = blockIdx.x;
    int tid = threadIdx.x;
    const float* row = Y + (size_t)t * DM;
    float4 v = *reinterpret_cast<const float4*>(row + tid * 4);
    float s = (v.x + v.y) + (v.z + v.w);
    __shared__ float sh[8];
#pragma unroll
    for (int o = 16; o > 0; o >>= 1) s += __shfl_xor_sync(0xffffffffu, s, o);
    if ((tid & 31) == 0) sh[tid >> 5] = s;
    __syncthreads();
    float tot = 0.0f;
#pragma unroll
    for (int i = 0; i < 8; i++) tot += sh[i];
    float mu = tot * (1.0f / 1024.0f);
    float dx0 = v.x - mu, dx1 = v.y - mu, dx2 = v.z - mu, dx3 = v.w - mu;
    float q = dx0 * dx0 + dx1 * dx1 + dx2 * dx2 + dx3 * dx3;
    __syncthreads();
#pragma unroll
    for (int o = 16; o > 0; o >>= 1) q += __shfl_xor_sync(0xffffffffu, q, o);
    if ((tid & 31) == 0) sh[tid >> 5] = q;
    __syncthreads();
    float qt = 0.0f;
#pragma unroll
    for (int i = 0; i < 8; i++) qt += sh[i];
    float var = qt * (1.0f / 1024.0f);
    float invs = rsqrtf(var + 1e-5f);
    float4 gg = *reinterpret_cast<const float4*>(g + tid * 4);
    float4 bb = *reinterpret_cast<const float4*>(b + tid * 4);
    float4 o4;
    o4.x = dx0 * invs * gg.x + bb.x;
    o4.y = dx1 * invs * gg.y + bb.y;
    o4.z = dx2 * invs * gg.z + bb.z;
    o4.w = dx3 * invs * gg.w + bb.w;
    *reinterpret_cast<float4*>(out + (size_t)t * DM + tid * 4) = o4;
}

// ---------------- launch ----------------
extern "C" void kernel_launch(void* const* d_in, const int* in_sizes, int n_in,
                              void* d_out, int out_size)
{
    (void)in_sizes; (void)n_in; (void)out_size;
    const float* x          = (const float*)d_in[0];
    const float* in_proj_w  = (const float*)d_in[1];
    const float* conv_w     = (const float*)d_in[2];
    const float* conv_b     = (const float*)d_in[3];
    const float* xproj_w    = (const float*)d_in[4];
    const float* dtproj_w   = (const float*)d_in[5];
    const float* dtproj_b   = (const float*)d_in[6];
    const float* D_param    = (const float*)d_in[7];
    const float* sw         = (const float*)d_in[8];
    const float* gate_w1    = (const float*)d_in[9];
    const float* gate_w2    = (const float*)d_in[10];
    const float* out_proj_w = (const float*)d_in[11];
    const float* ln_g       = (const float*)d_in[12];
    const float* ln_b       = (const float*)d_in[13];
    float* out = (float*)d_out;

    float *xz, *xs1, *xs2, *xc, *dt, *bc, *yb, *fused, *ctx, *g1, *pre, *yln;
    cudaGetSymbolAddress((void**)&xz,    g_xz);
    cudaGetSymbolAddress((void**)&xs1,   g_xs1);
    cudaGetSymbolAddress((void**)&xs2,   g_xs2);
    cudaGetSymbolAddress((void**)&xc,    g_xc);
    cudaGetSymbolAddress((void**)&dt,    g_dt);
    cudaGetSymbolAddress((void**)&bc,    g_bc);
    cudaGetSymbolAddress((void**)&yb,    g_y);
    cudaGetSymbolAddress((void**)&fused, g_fused);
    cudaGetSymbolAddress((void**)&ctx,   g_ctx);
    cudaGetSymbolAddress((void**)&g1,    g_g1);
    cudaGetSymbolAddress((void**)&pre,   g_pre);
    cudaGetSymbolAddress((void**)&yln,   g_yln);

    const int smem128 = 3 * (128 + 128) * SKS * 4;   // 110592 B
    const int smem64  = 3 * (64 + 128) * SKS * 4;    //  82944 B
    cudaFuncSetAttribute(gemm_tc<EPI_NONE, 128>, cudaFuncAttributeMaxDynamicSharedMemorySize, smem128);
    cudaFuncSetAttribute(gemm_tc<EPI_SILU, 64>,  cudaFuncAttributeMaxDynamicSharedMemorySize, smem64);
    cudaFuncSetAttribute(gemm_tc<EPI_GATE, 64>,  cudaFuncAttributeMaxDynamicSharedMemorySize, smem64);
    cudaFuncSetAttribute(gemm_tc<EPI_RES, 64>,   cudaFuncAttributeMaxDynamicSharedMemorySize, smem64);

    // 1) in_proj: xz[1024,4096] = x @ in_proj_w^T
    gemm_tc<EPI_NONE, 128><<<dim3(4096 / 128, 1024 / 128), 256, smem128>>>(
        x, 1024, in_proj_w, 1024, xz, 4096, 1024, nullptr, 0, nullptr, 0);

    // 2) downsample (both scales)
    downsample_all_kernel<<<((512 + 256) * DI + 255) / 256, 256>>>(xz, xs1, xs2);

    // 3) causal dwconv + silu (all scales)
    conv_all_kernel<<<(TROWS * DI + 255) / 256, 256>>>(xz, xs1, xs2, conv_w, conv_b, xc);

    // 4) xproj (smem-staged weights, conflict-free)
    xproj_all_kernel<<<TROWS / 8, 256>>>(xc, xproj_w, bc);

    // 5) dt (tiled with weight reuse)
    dt_all_kernel<<<dim3(TROWS / 16, DI / 256), 256>>>(bc, dtproj_w, dtproj_b, dt);

    // 6) scan (all scales)
    scan_all_kernel<<<384, 256>>>(dt, xc, bc, D_param, yb);

    // 7) fuse (upsample + weighted sum + ctx)
    fuse_kernel<<<(TL * DI + 255) / 256, 256>>>(yb, yb + 1024 * DI, yb + 1536 * DI,
                                                sw, fused, ctx);

    // 8) gate path + output projection
    gemm_tc<EPI_SILU, 64><<<dim3(1024 / 128, 1024 / 64), 256, smem64>>>(
        ctx, DI, gate_w1, DI, g1, 1024, DI, nullptr, 0, nullptr, 0);
    gemm_tc<EPI_GATE, 64><<<dim3(2048 / 128, 1024 / 64), 256, smem64>>>(
        g1, 1024, gate_w2, 1024, pre, DI, 1024, fused, DI, xz + 2048, 4096);
    gemm_tc<EPI_RES, 64><<<dim3(1024 / 128, 1024 / 64), 256, smem64>>>(
        pre, DI, out_proj_w, DI, yln, 1024, DI, x, 1024, nullptr, 0);

    // 9) layernorm -> d_out
    layernorm_kernel<<<1024, 256>>>(yln, ln_g, ln_b, out);
}

// round 16
// speedup vs baseline: 1.3219x; 1.0507x over previous
#include <cuda_runtime.h>
#include <math.h>
#include <stdint.h>

// ---------------- constants ----------------
#define TL   1024     // T_LEN
#define DM   1024     // DIM
#define DI   2048     // D_INNER
#define DS   16       // D_STATE
#define TROWS (1024 + 512 + 256)   // packed time rows across 3 scales

// ---------------- scratch (no cudaMalloc allowed) ----------------
__device__ float g_xz   [TL * 4096];          // xz = [x_in | gate]
__device__ float g_xs1  [512 * DI];
__device__ float g_xs2  [256 * DI];
__device__ float g_xc   [TROWS * DI];
__device__ float g_dt   [TROWS * DI];
__device__ float g_bc   [TROWS * 32];
__device__ float g_y    [TROWS * DI];
__device__ float g_fused[TL * DI];
__device__ float g_ctx  [TL * DI];
__device__ float g_g1   [TL * 1024];
__device__ float g_pre  [TL * DI];
__device__ float g_yln  [TL * DM];

// ---------------- helpers ----------------
static __device__ __forceinline__ float softplusf(float x) {
    return fmaxf(x, 0.0f) + log1pf(expf(-fabsf(x)));
}

static __device__ __forceinline__ void cp_async16(void* smem_dst, const void* gsrc) {
    uint32_t s = (uint32_t)__cvta_generic_to_shared(smem_dst);
    asm volatile("cp.async.cg.shared.global [%0], [%1], 16;\n" :: "r"(s), "l"(gsrc));
}
static __device__ __forceinline__ void cp_commit() {
    asm volatile("cp.async.commit_group;\n");
}
static __device__ __forceinline__ void cp_wait1() {
    asm volatile("cp.async.wait_group 1;\n" ::: "memory");
}

static __device__ __forceinline__ void mma_tf32(float* d, const uint32_t* a, const uint32_t* b) {
    asm volatile(
        "mma.sync.aligned.m16n8k8.row.col.f32.tf32.tf32.f32 "
        "{%0,%1,%2,%3}, {%4,%5,%6,%7}, {%8,%9}, {%0,%1,%2,%3};"
        : "+f"(d[0]), "+f"(d[1]), "+f"(d[2]), "+f"(d[3])
        : "r"(a[0]), "r"(a[1]), "r"(a[2]), "r"(a[3]), "r"(b[0]), "r"(b[1]));
}

// ---------------- TF32 tensor-core GEMM: C[M,N] = A[M,K] * W[N,K]^T ----------
// Block tile BM x 128, BK=32, 3-stage cp.async ring, 256 threads = 8 warps (2x4),
// warp tile (BM/2) x 32. fp32 raw bits fed to tf32 mma (HW truncation).
enum { EPI_NONE = 0, EPI_SILU = 1, EPI_GATE = 2, EPI_RES = 3 };

#define SKS 36   // smem row stride in floats (32 + 4 pad)

template <int EPI, int BM>
__global__ __launch_bounds__(256)
void gemm_tc(const float* __restrict__ A, int lda,
             const float* __restrict__ W, int ldw,
             float* __restrict__ C, int ldc, int K,
             const float* __restrict__ aux1, int ld1,
             const float* __restrict__ aux2, int ld2)
{
    constexpr int MT  = BM / 32;              // mmas in m per warp
    constexpr int NA4 = BM * 8 / 256;         // float4 copies per thread for A
    extern __shared__ __align__(16) float smem[];
    float* Asm = smem;                        // [3][BM][SKS]
    float* Wsm = smem + 3 * BM * SKS;         // [3][128][SKS]

    const int tid  = threadIdx.x;
    const int lane = tid & 31;
    const int wid  = tid >> 5;
    const int m0   = blockIdx.y * BM;
    const int n0   = blockIdx.x << 7;
    const int wm   = (wid >> 2) * (BM / 2);
    const int wn   = (wid & 3) << 5;
    const int gid  = lane >> 2;
    const int tig  = lane & 3;

    float acc[MT][4][4];
#pragma unroll
    for (int i = 0; i < MT; i++)
#pragma unroll
        for (int j = 0; j < 4; j++)
#pragma unroll
            for (int q = 0; q < 4; q++) acc[i][j][q] = 0.0f;

    const int KT = K >> 5;   // K/32 tiles

    auto issue = [&](int kt, int st) {
        const float* Ag = A + (size_t)m0 * lda + kt * 32;
        const float* Wg = W + (size_t)n0 * ldw + kt * 32;
        float* As = Asm + st * BM * SKS;
        float* Ws = Wsm + st * 128 * SKS;
#pragma unroll
        for (int i = 0; i < NA4; i++) {
            int idx4 = tid + i * 256;
            int row = idx4 >> 3;
            int col = (idx4 & 7) << 2;
            cp_async16(&As[row * SKS + col], Ag + (size_t)row * lda + col);
        }
#pragma unroll
        for (int i = 0; i < 4; i++) {
            int idx4 = tid + i * 256;
            int row = idx4 >> 3;
            int col = (idx4 & 7) << 2;
            cp_async16(&Ws[row * SKS + col], Wg + (size_t)row * ldw + col);
        }
    };

    issue(0, 0); cp_commit();
    issue(1, 1); cp_commit();

    for (int kt = 0; kt < KT; kt++) {
        const int st = kt % 3;
        cp_wait1();            // tile kt resident (tile kt+1 may still fly)
        __syncthreads();

        if (kt + 2 < KT) issue(kt + 2, (kt + 2) % 3);
        cp_commit();           // commit every iter (possibly empty) for group math

        const float* As = Asm + st * BM * SKS;
        const float* Ws = Wsm + st * 128 * SKS;

#pragma unroll
        for (int kk = 0; kk < 32; kk += 8) {
            uint32_t af[MT][4];
            uint32_t bf[4][2];
#pragma unroll
            for (int mt = 0; mt < MT; mt++) {
                int r = wm + (mt << 4) + gid;
                af[mt][0] = __float_as_uint(As[r * SKS + kk + tig]);
                af[mt][1] = __float_as_uint(As[(r + 8) * SKS + kk + tig]);
                af[mt][2] = __float_as_uint(As[r * SKS + kk + tig + 4]);
                af[mt][3] = __float_as_uint(As[(r + 8) * SKS + kk + tig + 4]);
            }
#pragma unroll
            for (int nt = 0; nt < 4; nt++) {
                int n = wn + (nt << 3) + gid;
                bf[nt][0] = __float_as_uint(Ws[n * SKS + kk + tig]);
                bf[nt][1] = __float_as_uint(Ws[n * SKS + kk + tig + 4]);
            }
#pragma unroll
            for (int mt = 0; mt < MT; mt++)
#pragma unroll
                for (int nt = 0; nt < 4; nt++)
                    mma_tf32(acc[mt][nt], af[mt], bf[nt]);
        }
    }

    // ---- epilogue ----
#pragma unroll
    for (int mt = 0; mt < MT; mt++) {
#pragma unroll
        for (int nt = 0; nt < 4; nt++) {
            int row0 = m0 + wm + (mt << 4) + gid;
            int col  = n0 + wn + (nt << 3) + (tig << 1);
#pragma unroll
            for (int half = 0; half < 2; half++) {
                int m = row0 + half * 8;
                float v0 = acc[mt][nt][half * 2 + 0];
                float v1 = acc[mt][nt][half * 2 + 1];
                if (EPI == EPI_SILU) {
                    v0 = v0 / (1.0f + expf(-v0));
                    v1 = v1 / (1.0f + expf(-v1));
                } else if (EPI == EPI_GATE) {
                    float f0 = aux1[(size_t)m * ld1 + col];
                    float f1 = aux1[(size_t)m * ld1 + col + 1];
                    float g0 = aux2[(size_t)m * ld2 + col];
                    float g1 = aux2[(size_t)m * ld2 + col + 1];
                    v0 = f0 * (1.0f / (1.0f + expf(-v0))) * (g0 / (1.0f + expf(-g0)));
                    v1 = f1 * (1.0f / (1.0f + expf(-v1))) * (g1 / (1.0f + expf(-g1)));
                } else if (EPI == EPI_RES) {
                    v0 += aux1[(size_t)m * ld1 + col];
                    v1 += aux1[(size_t)m * ld1 + col + 1];
                }
                *reinterpret_cast<float2*>(&C[(size_t)m * ldc + col]) = make_float2(v0, v1);
            }
        }
    }
}

// ---------------- downsample both scales in one launch ----------------
__global__ void downsample_all_kernel(const float* __restrict__ Xin,  // row stride 4096
                                      float* __restrict__ xs1, float* __restrict__ xs2)
{
    int idx = blockIdx.x * blockDim.x + threadIdx.x;   // over (512+256)*2048
    if (idx >= (512 + 256) * DI) return;
    int d = idx & (DI - 1);
    int r = idx >> 11;
    if (r < 512) {
        float s = Xin[(size_t)(r * 2) * 4096 + d] + Xin[(size_t)(r * 2 + 1) * 4096 + d];
        xs1[r * DI + d] = s * 0.5f;
    } else {
        int t = r - 512;
        float s = 0.0f;
#pragma unroll
        for (int q = 0; q < 4; q++) s += Xin[(size_t)(t * 4 + q) * 4096 + d];
        xs2[t * DI + d] = s * 0.25f;
    }
}

// ---------------- causal depthwise conv (K=4) + silu, all scales ----------
__global__ void conv_all_kernel(const float* __restrict__ xz,
                                const float* __restrict__ xs1,
                                const float* __restrict__ xs2,
                                const float* __restrict__ cw,   // [3][DI][4]
                                const float* __restrict__ cb,   // [3][DI]
                                float* __restrict__ xc)
{
    int idx = blockIdx.x * blockDim.x + threadIdx.x;   // over 1792*2048
    if (idx >= TROWS * DI) return;
    int d = idx & (DI - 1);
    int r = idx >> 11;

    int s, t;
    const float* X; int ldx;
    if (r < 1024)      { s = 0; t = r;        X = xz;  ldx = 4096; }
    else if (r < 1536) { s = 1; t = r - 1024; X = xs1; ldx = DI;   }
    else               { s = 2; t = r - 1536; X = xs2; ldx = DI;   }

    float4 w = *reinterpret_cast<const float4*>(cw + ((size_t)s * DI + d) * 4);
    float acc = cb[s * DI + d];
    if (t >= 3) {
        acc = fmaf(X[(size_t)(t - 3) * ldx + d], w.x, acc);
        acc = fmaf(X[(size_t)(t - 2) * ldx + d], w.y, acc);
        acc = fmaf(X[(size_t)(t - 1) * ldx + d], w.z, acc);
        acc = fmaf(X[(size_t)t * ldx + d],       w.w, acc);
    } else {
        const float wk[4] = {w.x, w.y, w.z, w.w};
#pragma unroll
        for (int k = 0; k < 4; k++) {
            int tt = t - 3 + k;
            if (tt >= 0) acc = fmaf(X[(size_t)tt * ldx + d], wk[k], acc);
        }
    }
    xc[idx] = acc / (1.0f + expf(-acc));   // silu
}

// ---------------- xproj: bc[r,32] = xc[r,:] @ xw_s[32,DI]^T ----------------
// Block = 8 warps = 8 rows; lane j = output col j. Weight chunks staged in
// smem. Row stride 260 floats: 16B-aligned rows, bank base 4j -> each
// quarter-warp LDS.128 phase tiles all 32 banks (conflict-free).
// 4 independent accumulators break the FMA dependency chain (ILP=4).
#define XK 256
#define WSTR 260
__global__ __launch_bounds__(256)
void xproj_all_kernel(const float* __restrict__ xc, const float* __restrict__ xproj_w,
                      float* __restrict__ bc)
{
    __shared__ __align__(16) float ws[32][WSTR];

    const int warp = threadIdx.x >> 5;
    const int j    = threadIdx.x & 31;
    const int r0   = blockIdx.x * 8;             // 1024,1536 divisible by 8: no cross
    const int r    = r0 + warp;
    const int s    = (r0 < 1024) ? 0 : (r0 < 1536 ? 1 : 2);
    const float* wbase = xproj_w + (size_t)s * 32 * DI;
    const float* xrow  = xc + (size_t)r * DI;

    float a0 = 0.f, a1 = 0.f, a2 = 0.f, a3 = 0.f;
    for (int k0 = 0; k0 < DI; k0 += XK) {
        __syncthreads();   // previous chunk fully consumed
        // stage ws[32][XK]: 8192 floats, 256 threads x 8 float4 each, coalesced
#pragma unroll
        for (int i = threadIdx.x * 4; i < 32 * XK; i += 256 * 4) {
            int row = i >> 8;          // i / XK
            int col = i & (XK - 1);    // i % XK
            float4 v = *reinterpret_cast<const float4*>(wbase + (size_t)row * DI + k0 + col);
            *reinterpret_cast<float4*>(&ws[row][col]) = v;
        }
        __syncthreads();
#pragma unroll 4
        for (int k = 0; k < XK; k += 16) {
            float4 x0 = *reinterpret_cast<const float4*>(xrow + k0 + k);       // broadcast
            float4 x1 = *reinterpret_cast<const float4*>(xrow + k0 + k + 4);
            float4 x2 = *reinterpret_cast<const float4*>(xrow + k0 + k + 8);
            float4 x3 = *reinterpret_cast<const float4*>(xrow + k0 + k + 12);
            float4 w0 = *reinterpret_cast<const float4*>(&ws[j][k]);
            float4 w1 = *reinterpret_cast<const float4*>(&ws[j][k + 4]);
            float4 w2 = *reinterpret_cast<const float4*>(&ws[j][k + 8]);
            float4 w3 = *reinterpret_cast<const float4*>(&ws[j][k + 12]);
            a0 = fmaf(x0.x, w0.x, a0); a0 = fmaf(x0.y, w0.y, a0);
            a0 = fmaf(x0.z, w0.z, a0); a0 = fmaf(x0.w, w0.w, a0);
            a1 = fmaf(x1.x, w1.x, a1); a1 = fmaf(x1.y, w1.y, a1);
            a1 = fmaf(x1.z, w1.z, a1); a1 = fmaf(x1.w, w1.w, a1);
            a2 = fmaf(x2.x, w2.x, a2); a2 = fmaf(x2.y, w2.y, a2);
            a2 = fmaf(x2.z, w2.z, a2); a2 = fmaf(x2.w, w2.w, a2);
            a3 = fmaf(x3.x, w3.x, a3); a3 = fmaf(x3.y, w3.y, a3);
            a3 = fmaf(x3.z, w3.z, a3); a3 = fmaf(x3.w, w3.w, a3);
        }
    }
    bc[r * 32 + j] = (a0 + a1) + (a2 + a3);
}

// ---------------- dt: tiled, weight-reuse version ----------
// block = 256 threads = 256 channels; 16 rows per block.
// grid.x = TROWS/16 (row tiles, never crossing scale boundary), grid.y = DI/256.
__global__ __launch_bounds__(256)
void dt_all_kernel(const float* __restrict__ bc, const float* __restrict__ dtproj_w,
                   const float* __restrict__ dtproj_b, float* __restrict__ dt)
{
    __shared__ float Bs[16][32];

    const int r0 = blockIdx.x * 16;
    const int d  = blockIdx.y * 256 + threadIdx.x;
    const int s  = (r0 < 1024) ? 0 : (r0 < 1536 ? 1 : 2);

    // stage the 16 bc rows: 512 floats, 256 threads -> 2 each (coalesced)
#pragma unroll
    for (int i = threadIdx.x; i < 16 * 32; i += 256) {
        Bs[i >> 5][i & 31] = bc[(r0 + (i >> 5)) * 32 + (i & 31)];
    }

    // per-thread weights: 16 floats, loaded once, reused over 16 rows
    const float* wrow = dtproj_w + ((size_t)s * DI + d) * 16;
    float4 w0 = *reinterpret_cast<const float4*>(wrow);
    float4 w1 = *reinterpret_cast<const float4*>(wrow + 4);
    float4 w2 = *reinterpret_cast<const float4*>(wrow + 8);
    float4 w3 = *reinterpret_cast<const float4*>(wrow + 12);
    const float bias = dtproj_b[s * DI + d];

    __syncthreads();

#pragma unroll 4
    for (int rr = 0; rr < 16; rr++) {
        const float* B = Bs[rr];
        float acc = bias;
        acc = fmaf(B[0],  w0.x, acc); acc = fmaf(B[1],  w0.y, acc);
        acc = fmaf(B[2],  w0.z, acc); acc = fmaf(B[3],  w0.w, acc);
        acc = fmaf(B[4],  w1.x, acc); acc = fmaf(B[5],  w1.y, acc);
        acc = fmaf(B[6],  w1.z, acc); acc = fmaf(B[7],  w1.w, acc);
        acc = fmaf(B[8],  w2.x, acc); acc = fmaf(B[9],  w2.y, acc);
        acc = fmaf(B[10], w2.z, acc); acc = fmaf(B[11], w2.w, acc);
        acc = fmaf(B[12], w3.x, acc); acc = fmaf(B[13], w3.y, acc);
        acc = fmaf(B[14], w3.z, acc); acc = fmaf(B[15], w3.w, acc);
        dt[(size_t)(r0 + rr) * DI + d] = softplusf(softplusf(acc));
    }
}

// ---------------- SSM scan (all 3 scales in one launch, 1-iter prefetch) ----
__global__ __launch_bounds__(256)
void scan_all_kernel(const float* __restrict__ dtb_, const float* __restrict__ xcb_,
                     const float* __restrict__ bcb_, const float* __restrict__ Dp_,
                     float* __restrict__ yb_)
{
    int gw   = (blockIdx.x * 256 + threadIdx.x) >> 5;   // 0..3071
    int s    = gw >> 10;                                 // scale 0..2
    int w    = gw & 1023;
    int lane = threadIdx.x & 31;
    int d    = w * 2 + (lane >> 4);
    int n    = lane & 15;
    int T    = 1024 >> s;

    const int xo  = (s == 0) ? 0 : (s == 1 ? 1024 * DI : 1536 * DI);
    const int bco = (s == 0) ? 0 : (s == 1 ? 1024 * 32 : 1536 * 32);

    const float* dt = dtb_ + xo;
    const float* xc = xcb_ + xo;
    const float* bc = bcb_ + bco;
    float*       y  = yb_ + xo;

    const float A  = -(float)(n + 1);
    const float Dv = Dp_[s * DI + d];

    float h = 0.0f;
    float dtv = dt[d];
    float xcv = xc[d];
    float Bv  = bc[n];
    float Cv  = bc[16 + n];

    for (int t = 0; t < T; t++) {
        float dtn = 0.f, xcn = 0.f, Bn = 0.f, Cn = 0.f;
        if (t + 1 < T) {
            dtn = dt[(size_t)(t + 1) * DI + d];
            xcn = xc[(size_t)(t + 1) * DI + d];
            Bn  = bc[(t + 1) * 32 + n];
            Cn  = bc[(t + 1) * 32 + 16 + n];
        }
        float a = __expf(dtv * A);
        a = fmaxf(a, 1e-38f);
        float b = dtv * Bv * xcv;
        b = fmaxf(b, 1e-38f);
        h = fmaf(a, h, b);
        float c = Cv * h;
        c += __shfl_xor_sync(0xffffffffu, c, 8);
        c += __shfl_xor_sync(0xffffffffu, c, 4);
        c += __shfl_xor_sync(0xffffffffu, c, 2);
        c += __shfl_xor_sync(0xffffffffu, c, 1);
        if (n == 0) y[(size_t)t * DI + d] = c + Dv * xcv;
        dtv = dtn; xcv = xcn; Bv = Bn; Cv = Cn;
    }
}

// ---------------- fuse: upsample + softmax-weighted sum + ctx ----------------
__global__ void fuse_kernel(const float* __restrict__ y0, const float* __restrict__ y1,
                            const float* __restrict__ y2, const float* __restrict__ sw,
                            float* __restrict__ fused, float* __restrict__ ctx)
{
    int idx = blockIdx.x * blockDim.x + threadIdx.x;
    if (idx >= TL * DI) return;
    int d = idx & (DI - 1);
    int t = idx >> 11;

    float w0 = sw[0], w1 = sw[1], w2 = sw[2];
    float m = fmaxf(w0, fmaxf(w1, w2));
    float e0 = expf(w0 - m), e1 = expf(w1 - m), e2 = expf(w2 - m);
    float inv = 1.0f / (e0 + e1 + e2);

    float o0 = y0[idx];

    float p1 = (t + 0.5f) * 0.5f - 0.5f;
    p1 = fminf(fmaxf(p1, 0.0f), 511.0f);
    int lo1 = (int)floorf(p1);
    int hi1 = min(lo1 + 1, 511);
    float f1 = p1 - (float)lo1;
    float o1 = y1[(size_t)lo1 * DI + d] * (1.0f - f1) + y1[(size_t)hi1 * DI + d] * f1;

    float p2 = (t + 0.5f) * 0.25f - 0.5f;
    p2 = fminf(fmaxf(p2, 0.0f), 255.0f);
    int lo2 = (int)floorf(p2);
    int hi2 = min(lo2 + 1, 255);
    float f2 = p2 - (float)lo2;
    float o2 = y2[(size_t)lo2 * DI + d] * (1.0f - f2) + y2[(size_t)hi2 * DI + d] * f2;

    fused[idx] = (e0 * o0 + e1 * o1 + e2 * o2) * inv;
    ctx[idx]   = (o0 + o1 + o2) * (1.0f / 3.0f);
}

// ---------------- layernorm over last dim (1024) ----------------
__global__ __launch_bounds__(256)
void layernorm_kernel(const float* __restrict__ Y, const float* __restrict__ g,
                      const float* __restrict__ b, float* __restrict__ out)
{
    int t = blockIdx.x;
    int tid = threadIdx.x;
    const float* row = Y + (size_t)t * DM;
    float4 v = *reinterpret_cast<const float4*>(row + tid * 4);
    float s = (v.x + v.y) + (v.z + v.w);
    __shared__ float sh[8];
#pragma unroll
    for (int o = 16; o > 0; o >>= 1) s += __shfl_xor_sync(0xffffffffu, s, o);
    if ((tid & 31) == 0) sh[tid >> 5] = s;
    __syncthreads();
    float tot = 0.0f;
#pragma unroll
    for (int i = 0; i < 8; i++) tot += sh[i];
    float mu = tot * (1.0f / 1024.0f);
    float dx0 = v.x - mu, dx1 = v.y - mu, dx2 = v.z - mu, dx3 = v.w - mu;
    float q = dx0 * dx0 + dx1 * dx1 + dx2 * dx2 + dx3 * dx3;
    __syncthreads();
#pragma unroll
    for (int o = 16; o > 0; o >>= 1) q += __shfl_xor_sync(0xffffffffu, q, o);
    if ((tid & 31) == 0) sh[tid >> 5] = q;
    __syncthreads();
    float qt = 0.0f;
#pragma unroll
    for (int i = 0; i < 8; i++) qt += sh[i];
    float var = qt * (1.0f / 1024.0f);
    float invs = rsqrtf(var + 1e-5f);
    float4 gg = *reinterpret_cast<const float4*>(g + tid * 4);
    float4 bb = *reinterpret_cast<const float4*>(b + tid * 4);
    float4 o4;
    o4.x = dx0 * invs * gg.x + bb.x;
    o4.y = dx1 * invs * gg.y + bb.y;
    o4.z = dx2 * invs * gg.z + bb.z;
    o4.w = dx3 * invs * gg.w + bb.w;
    *reinterpret_cast<float4*>(out + (size_t)t * DM + tid * 4) = o4;
}

// ---------------- launch ----------------
extern "C" void kernel_launch(void* const* d_in, const int* in_sizes, int n_in,
                              void* d_out, int out_size)
{
    (void)in_sizes; (void)n_in; (void)out_size;
    const float* x          = (const float*)d_in[0];
    const float* in_proj_w  = (const float*)d_in[1];
    const float* conv_w     = (const float*)d_in[2];
    const float* conv_b     = (const float*)d_in[3];
    const float* xproj_w    = (const float*)d_in[4];
    const float* dtproj_w   = (const float*)d_in[5];
    const float* dtproj_b   = (const float*)d_in[6];
    const float* D_param    = (const float*)d_in[7];
    const float* sw         = (const float*)d_in[8];
    const float* gate_w1    = (const float*)d_in[9];
    const float* gate_w2    = (const float*)d_in[10];
    const float* out_proj_w = (const float*)d_in[11];
    const float* ln_g       = (const float*)d_in[12];
    const float* ln_b       = (const float*)d_in[13];
    float* out = (float*)d_out;

    float *xz, *xs1, *xs2, *xc, *dt, *bc, *yb, *fused, *ctx, *g1, *pre, *yln;
    cudaGetSymbolAddress((void**)&xz,    g_xz);
    cudaGetSymbolAddress((void**)&xs1,   g_xs1);
    cudaGetSymbolAddress((void**)&xs2,   g_xs2);
    cudaGetSymbolAddress((void**)&xc,    g_xc);
    cudaGetSymbolAddress((void**)&dt,    g_dt);
    cudaGetSymbolAddress((void**)&bc,    g_bc);
    cudaGetSymbolAddress((void**)&yb,    g_y);
    cudaGetSymbolAddress((void**)&fused, g_fused);
    cudaGetSymbolAddress((void**)&ctx,   g_ctx);
    cudaGetSymbolAddress((void**)&g1,    g_g1);
    cudaGetSymbolAddress((void**)&pre,   g_pre);
    cudaGetSymbolAddress((void**)&yln,   g_yln);

    const int smem128 = 3 * (128 + 128) * SKS * 4;   // 110592 B
    const int smem64  = 3 * (64 + 128) * SKS * 4;    //  82944 B
    cudaFuncSetAttribute(gemm_tc<EPI_NONE, 128>, cudaFuncAttributeMaxDynamicSharedMemorySize, smem128);
    cudaFuncSetAttribute(gemm_tc<EPI_SILU, 64>,  cudaFuncAttributeMaxDynamicSharedMemorySize, smem64);
    cudaFuncSetAttribute(gemm_tc<EPI_GATE, 64>,  cudaFuncAttributeMaxDynamicSharedMemorySize, smem64);
    cudaFuncSetAttribute(gemm_tc<EPI_RES, 64>,   cudaFuncAttributeMaxDynamicSharedMemorySize, smem64);

    // 1) in_proj: xz[1024,4096] = x @ in_proj_w^T
    gemm_tc<EPI_NONE, 128><<<dim3(4096 / 128, 1024 / 128), 256, smem128>>>(
        x, 1024, in_proj_w, 1024, xz, 4096, 1024, nullptr, 0, nullptr, 0);

    // 2) downsample (both scales)
    downsample_all_kernel<<<((512 + 256) * DI + 255) / 256, 256>>>(xz, xs1, xs2);

    // 3) causal dwconv + silu (all scales)
    conv_all_kernel<<<(TROWS * DI + 255) / 256, 256>>>(xz, xs1, xs2, conv_w, conv_b, xc);

    // 4) xproj (smem-staged weights, LDS.128 conflict-free, ILP=4)
    xproj_all_kernel<<<TROWS / 8, 256>>>(xc, xproj_w, bc);

    // 5) dt (tiled with weight reuse)
    dt_all_kernel<<<dim3(TROWS / 16, DI / 256), 256>>>(bc, dtproj_w, dtproj_b, dt);

    // 6) scan (all scales)
    scan_all_kernel<<<384, 256>>>(dt, xc, bc, D_param, yb);

    // 7) fuse (upsample + weighted sum + ctx)
    fuse_kernel<<<(TL * DI + 255) / 256, 256>>>(yb, yb + 1024 * DI, yb + 1536 * DI,
                                                sw, fused, ctx);

    // 8) gate path + output projection
    gemm_tc<EPI_SILU, 64><<<dim3(1024 / 128, 1024 / 64), 256, smem64>>>(
        ctx, DI, gate_w1, DI, g1, 1024, DI, nullptr, 0, nullptr, 0);
    gemm_tc<EPI_GATE, 64><<<dim3(2048 / 128, 1024 / 64), 256, smem64>>>(
        g1, 1024, gate_w2, 1024, pre, DI, 1024, fused, DI, xz + 2048, 4096);
    gemm_tc<EPI_RES, 64><<<dim3(1024 / 128, 1024 / 64), 256, smem64>>>(
        pre, DI, out_proj_w, DI, yln, 1024, DI, x, 1024, nullptr, 0);

    // 9) layernorm -> d_out
    layernorm_kernel<<<1024, 256>>>(yln, ln_g, ln_b, out);
}